// round 2
// baseline (speedup 1.0000x reference)
#include <cuda_runtime.h>
#include <math.h>

#define D  1024
#define NC 16
#define NS 4096
#define MQ 4096
#define BS 128
#define NB 8

// ---------------- scratch (device globals: allocation-free contract) ----------------
__device__ float d_Xs[(size_t)NS * D];                // class-sorted X
__device__ int   d_counts[NC];
__device__ int   d_offsets[NC + 1];
__device__ int   d_dst[NS];
__device__ float d_mu[NC * D];
__device__ float d_base[(size_t)D * D];               // L L^T + kap m m^T (lower)
__device__ float d_sigma[(size_t)NC * D * D];         // sigma -> cholesky L (lower)
__device__ float d_invL[(size_t)NC * D * D];          // L^-1 (lower, upper zeroed)
__device__ float d_acc[(size_t)MQ * NC];              // 0.1 * ||diff||^2

// ---------------- small setup kernels ----------------
__global__ void k_count(const int* __restrict__ y) {
    __shared__ int cnt[NC];
    int t = threadIdx.x;
    if (t < NC) cnt[t] = 0;
    __syncthreads();
    for (int n = t; n < NS; n += blockDim.x) atomicAdd(&cnt[y[n]], 1);
    __syncthreads();
    if (t == 0) {
        int off = 0;
        for (int c = 0; c < NC; c++) { d_counts[c] = cnt[c]; d_offsets[c] = off; off += cnt[c]; }
        d_offsets[NC] = off;
    }
}

// deterministic stable rank within class (no float atomics anywhere)
__global__ void k_rank(const int* __restrict__ y) {
    __shared__ int sy[NS];
    for (int i = threadIdx.x; i < NS; i += blockDim.x) sy[i] = y[i];
    __syncthreads();
    int n = blockIdx.x * blockDim.x + threadIdx.x;
    int c = sy[n];
    int r = 0;
    for (int p = 0; p < n; p++) r += (sy[p] == c);
    d_dst[n] = d_offsets[c] + r;
}

__global__ void k_scatter(const float* __restrict__ X) {
    int n = blockIdx.x;
    int dst = d_dst[n];
    const float* src = X + (size_t)n * D;
    float* dp = d_Xs + (size_t)dst * D;
    for (int j = threadIdx.x; j < D; j += blockDim.x) dp[j] = src[j];
}

__global__ void k_mu(const float* __restrict__ m, const float* __restrict__ kappa) {
    int c = blockIdx.y;
    int j = blockIdx.x * blockDim.x + threadIdx.x;
    int ks = d_offsets[c], ke = d_offsets[c + 1];
    float s = 0.f;
    for (int r = ks; r < ke; r++) s += d_Xs[(size_t)r * D + j];
    float kap = fabsf(*kappa) + 1e-6f;
    float Nj = (float)(ke - ks);
    d_mu[c * D + j] = (kap * m[j] + s) / (kap + Nj);
}

// ---------------- shared GEMM micro-kernel (128x128 tile, 256 thr, 8x8 micro) ----------------
__device__ __forceinline__ void mm32(const float* As, const float* Bs, int r0, int c0,
                                     float acc[8][8]) {
#pragma unroll 4
    for (int kk = 0; kk < 32; kk++) {
        float a[8], b[8];
#pragma unroll
        for (int u = 0; u < 8; u++) a[u] = As[kk * 129 + r0 + u];
#pragma unroll
        for (int u = 0; u < 8; u++) b[u] = Bs[kk * 129 + c0 + u];
#pragma unroll
        for (int i = 0; i < 8; i++)
#pragma unroll
            for (int j = 0; j < 8; j++) acc[i][j] = fmaf(a[i], b[j], acc[i][j]);
    }
}

__device__ __forceinline__ float Lval(const float* diag, const float* TL, int i, int k) {
    if (k < i) return TL[(size_t)i * D + k];
    if (k == i) return fabsf(diag[i]);
    return 0.f;
}

// base = L L^T + kap * m m^T  (lower tiles only)
__global__ void k_base(const float* __restrict__ diag, const float* __restrict__ TL,
                       const float* __restrict__ m, const float* __restrict__ kappa) {
    int bi = blockIdx.x, bj = blockIdx.y;
    if (bj > bi) return;
    __shared__ float As[32 * 129], Bs[32 * 129];
    int tid = threadIdx.x, tx = tid & 15, ty = tid >> 4;
    int r0 = ty * 8, c0 = tx * 8;
    float acc[8][8] = {};
    int kmax = (bj + 1) * BS;
    for (int kc = 0; kc < kmax; kc += 32) {
        __syncthreads();
#pragma unroll
        for (int l = 0; l < 16; l++) {
            int idx = tid + 256 * l;
            int i = idx >> 5, kk = idx & 31;
            As[kk * 129 + i] = Lval(diag, TL, bi * BS + i, kc + kk);
            Bs[kk * 129 + i] = Lval(diag, TL, bj * BS + i, kc + kk);
        }
        __syncthreads();
        mm32(As, Bs, r0, c0, acc);
    }
    float kap = fabsf(*kappa) + 1e-6f;
#pragma unroll
    for (int i = 0; i < 8; i++) {
        int gi = bi * BS + r0 + i;
#pragma unroll
        for (int j = 0; j < 8; j++) {
            int gj = bj * BS + c0 + j;
            if (gj <= gi)
                d_base[(size_t)gi * D + gj] = acc[i][j] + kap * m[gi] * m[gj];
        }
    }
}

// sigma[c] lower = (base + S_c - (kap+Nj) mu mu^T) / (nu_ + Nj + d + 2)
__global__ void k_sigma(const float* __restrict__ kappa, const float* __restrict__ nu) {
    int bi = blockIdx.x, bj = blockIdx.y, c = blockIdx.z;
    if (bj > bi) return;
    __shared__ float As[32 * 129], Bs[32 * 129];
    int tid = threadIdx.x, tx = tid & 15, ty = tid >> 4;
    int r0 = ty * 8, c0 = tx * 8;
    float acc[8][8] = {};
    int ks = d_offsets[c], ke = d_offsets[c + 1];
    for (int k0 = ks; k0 < ke; k0 += 32) {
        __syncthreads();
#pragma unroll
        for (int l = 0; l < 16; l++) {
            int idx = tid + 256 * l;
            int kk = idx >> 7, i = idx & 127;
            int krow = k0 + kk;
            float av = 0.f, bv = 0.f;
            if (krow < ke) {
                av = d_Xs[(size_t)krow * D + bi * BS + i];
                bv = d_Xs[(size_t)krow * D + bj * BS + i];
            }
            As[kk * 129 + i] = av;
            Bs[kk * 129 + i] = bv;
        }
        __syncthreads();
        mm32(As, Bs, r0, c0, acc);
    }
    float kap = fabsf(*kappa) + 1e-6f;
    float Nj = (float)(ke - ks);
    float nuv = fmaxf(*nu, (float)(D - 1) + 1e-6f);
    float invden = 1.f / (nuv + Nj + (float)D + 2.f);
    float coef = kap + Nj;
    float* Sg = d_sigma + (size_t)c * D * D;
#pragma unroll
    for (int i = 0; i < 8; i++) {
        int gi = bi * BS + r0 + i;
        float mi = d_mu[c * D + gi];
#pragma unroll
        for (int j = 0; j < 8; j++) {
            int gj = bj * BS + c0 + j;
            if (gj <= gi) {
                float mj = d_mu[c * D + gj];
                Sg[(size_t)gi * D + gj] =
                    (d_base[(size_t)gi * D + gj] + acc[i][j] - coef * mi * mj) * invden;
            }
        }
    }
}

// factor 128x128 diag block in smem; also produce its triangular inverse
__global__ void k_chol_diag(int kb) {
    extern __shared__ float sh[];
    float* A = sh;                 // 128 x 129
    float* V = sh + 128 * 129;     // 128 x 129
    int c = blockIdx.x;
    int t = threadIdx.x;           // 128 threads
    float* Sg = d_sigma + (size_t)c * D * D;
    for (int idx = t; idx < BS * BS; idx += BS) {
        int r = idx >> 7, col = idx & 127;
        A[r * 129 + col] = Sg[(size_t)(kb * BS + r) * D + kb * BS + col];
    }
    __syncthreads();
    for (int j = 0; j < BS; j++) {
        if (t == j) A[j * 129 + j] = sqrtf(A[j * 129 + j]);
        __syncthreads();
        float dj = A[j * 129 + j];
        if (t > j) A[t * 129 + j] /= dj;
        __syncthreads();
        if (t > j) {
            float l = A[t * 129 + j];
            for (int col = j + 1; col <= t; col++)
                A[t * 129 + col] -= l * A[col * 129 + j];
        }
        __syncthreads();
    }
    for (int idx = t; idx < BS * BS; idx += BS) {
        int r = idx >> 7, col = idx & 127;
        if (col <= r) Sg[(size_t)(kb * BS + r) * D + kb * BS + col] = A[r * 129 + col];
    }
    // forward substitution: thread t solves L z = e_t (column t of inverse)
    for (int r = 0; r < BS; r++) {
        float v;
        if (r < t) v = 0.f;
        else if (r == t) v = 1.f / A[r * 129 + r];
        else {
            float s = 0.f;
            for (int q = t; q < r; q++) s = fmaf(A[r * 129 + q], V[q * 129 + t], s);
            v = -s / A[r * 129 + r];
        }
        V[r * 129 + t] = v;
    }
    __syncthreads();
    float* iL = d_invL + (size_t)c * D * D;
    for (int idx = t; idx < BS * BS; idx += BS) {
        int r = idx >> 7, col = idx & 127;
        iL[(size_t)(kb * BS + r) * D + kb * BS + col] = (col <= r) ? V[r * 129 + col] : 0.f;
    }
}

// panel: L(bi,kb) = A(bi,kb) * invLkk^T
__global__ void k_panel(int kb) {
    int bi = blockIdx.x, c = blockIdx.y;
    if (bi <= kb) return;
    __shared__ float As[32 * 129], Bs[32 * 129];
    int tid = threadIdx.x, tx = tid & 15, ty = tid >> 4;
    int r0 = ty * 8, c0 = tx * 8;
    float acc[8][8] = {};
    float* Sg = d_sigma + (size_t)c * D * D;
    const float* iL = d_invL + (size_t)c * D * D;
    for (int kc = 0; kc < BS; kc += 32) {
        __syncthreads();
#pragma unroll
        for (int l = 0; l < 16; l++) {
            int idx = tid + 256 * l;
            int r = idx >> 5, kk = idx & 31;
            As[kk * 129 + r] = Sg[(size_t)(bi * BS + r) * D + kb * BS + kc + kk];
            Bs[kk * 129 + r] = iL[(size_t)(kb * BS + r) * D + kb * BS + kc + kk];
        }
        __syncthreads();
        mm32(As, Bs, r0, c0, acc);
    }
    __syncthreads();
#pragma unroll
    for (int i = 0; i < 8; i++)
#pragma unroll
        for (int j = 0; j < 8; j++)
            Sg[(size_t)(bi * BS + r0 + i) * D + kb * BS + c0 + j] = acc[i][j];
}

// trailing update: A(bi,bj) -= P_bi P_bj^T  for kb < bj <= bi
__global__ void k_syrk(int kb) {
    int bi = blockIdx.x, bj = blockIdx.y, c = blockIdx.z;
    if (bj <= kb || bj > bi) return;
    __shared__ float As[32 * 129], Bs[32 * 129];
    int tid = threadIdx.x, tx = tid & 15, ty = tid >> 4;
    int r0 = ty * 8, c0 = tx * 8;
    float acc[8][8] = {};
    float* Sg = d_sigma + (size_t)c * D * D;
    for (int kc = 0; kc < BS; kc += 32) {
        __syncthreads();
#pragma unroll
        for (int l = 0; l < 16; l++) {
            int idx = tid + 256 * l;
            int r = idx >> 5, kk = idx & 31;
            As[kk * 129 + r] = Sg[(size_t)(bi * BS + r) * D + kb * BS + kc + kk];
            Bs[kk * 129 + r] = Sg[(size_t)(bj * BS + r) * D + kb * BS + kc + kk];
        }
        __syncthreads();
        mm32(As, Bs, r0, c0, acc);
    }
    __syncthreads();
#pragma unroll
    for (int i = 0; i < 8; i++) {
        int gi = bi * BS + r0 + i;
#pragma unroll
        for (int j = 0; j < 8; j++) {
            int gj = bj * BS + c0 + j;
            if (bi != bj || gj <= gi)
                Sg[(size_t)gi * D + gj] -= acc[i][j];
        }
    }
}

// blocked trtri: invL(bi,bj) = -invL(bi,bi) * sum_{k=bj..bi-1} L(bi,k) invL(k,bj)
__global__ void k_trtri(int s) {
    int bj = blockIdx.x, c = blockIdx.y;
    if (bj + s >= NB) return;
    int bi = bj + s;
    extern __shared__ float sh[];
    float* Ts = sh;                    // 128 x 129
    float* As = sh + 128 * 129;        // 32 x 129
    float* Bs = As + 32 * 129;         // 32 x 129
    int tid = threadIdx.x, tx = tid & 15, ty = tid >> 4;
    int r0 = ty * 8, c0 = tx * 8;
    const float* Sg = d_sigma + (size_t)c * D * D;
    float* iL = d_invL + (size_t)c * D * D;
    float acc[8][8] = {};
    for (int kb = bj; kb < bi; kb++) {
        for (int kc = 0; kc < BS; kc += 32) {
            __syncthreads();
#pragma unroll
            for (int l = 0; l < 16; l++) {
                int idx = tid + 256 * l;
                {
                    int r = idx >> 5, kk = idx & 31;
                    As[kk * 129 + r] = Sg[(size_t)(bi * BS + r) * D + kb * BS + kc + kk];
                }
                {
                    int kk = idx >> 7, cc = idx & 127;
                    Bs[kk * 129 + cc] = iL[(size_t)(kb * BS + kc + kk) * D + bj * BS + cc];
                }
            }
            __syncthreads();
            mm32(As, Bs, r0, c0, acc);
        }
    }
    __syncthreads();
#pragma unroll
    for (int i = 0; i < 8; i++)
#pragma unroll
        for (int j = 0; j < 8; j++)
            Ts[(r0 + i) * 129 + c0 + j] = acc[i][j];
    __syncthreads();
    float a2[8][8] = {};
    for (int kc = 0; kc < BS; kc += 32) {
        __syncthreads();
#pragma unroll
        for (int l = 0; l < 16; l++) {
            int idx = tid + 256 * l;
            int r = idx >> 5, kk = idx & 31;
            As[kk * 129 + r] = iL[(size_t)(bi * BS + r) * D + bi * BS + kc + kk];
        }
        __syncthreads();
#pragma unroll 4
        for (int kk = 0; kk < 32; kk++) {
            float a[8], b[8];
#pragma unroll
            for (int u = 0; u < 8; u++) a[u] = As[kk * 129 + r0 + u];
#pragma unroll
            for (int u = 0; u < 8; u++) b[u] = Ts[(kc + kk) * 129 + c0 + u];
#pragma unroll
            for (int i = 0; i < 8; i++)
#pragma unroll
                for (int j = 0; j < 8; j++) a2[i][j] = fmaf(a[i], b[j], a2[i][j]);
        }
    }
#pragma unroll
    for (int i = 0; i < 8; i++)
#pragma unroll
        for (int j = 0; j < 8; j++)
            iL[(size_t)(bi * BS + r0 + i) * D + bj * BS + c0 + j] = -a2[i][j];
}

// 0.1 * ||xq - mu_c||^2
__global__ void k_nd(const float* __restrict__ Xq) {
    int c = blockIdx.y;
    int warp = threadIdx.x >> 5, lane = threadIdx.x & 31;
    int mr = blockIdx.x * 8 + warp;
    const float* xq = Xq + (size_t)mr * D;
    const float* mu = d_mu + c * D;
    float s = 0.f;
    for (int k = lane; k < D; k += 32) {
        float df = xq[k] - mu[k];
        s = fmaf(df, df, s);
    }
#pragma unroll
    for (int o = 16; o; o >>= 1) s += __shfl_xor_sync(0xffffffffu, s, o);
    if (!lane) d_acc[(size_t)mr * NC + c] = 0.1f * s;
}

// main predict: column norms of Z = invL * (Xq - mu)^T, triangular k-loop; fused epilogue
__global__ void k_sq(const float* __restrict__ Xq, float* __restrict__ out) {
    int mb = blockIdx.x, c = blockIdx.y;
    int m0 = mb * BS;
    __shared__ float As[32 * 129], Bs[32 * 129];
    __shared__ float Pr[256 * 8];
    int tid = threadIdx.x, tx = tid & 15, ty = tid >> 4;
    int r0 = ty * 8, c0 = tx * 8;
    const float* iL = d_invL + (size_t)c * D * D;
    const float* mu = d_mu + c * D;
    float col[8] = {};
    for (int bi = 0; bi < NB; bi++) {
        float acc[8][8] = {};
        for (int kt = 0; kt <= bi; kt++) {
            for (int kc = 0; kc < BS; kc += 32) {
                int k0 = kt * BS + kc;
                __syncthreads();
#pragma unroll
                for (int l = 0; l < 16; l++) {
                    int idx = tid + 256 * l;
                    int r = idx >> 5, kk = idx & 31;
                    As[kk * 129 + r] = iL[(size_t)(bi * BS + r) * D + k0 + kk];
                    Bs[kk * 129 + r] = Xq[(size_t)(m0 + r) * D + k0 + kk] - mu[k0 + kk];
                }
                __syncthreads();
                mm32(As, Bs, r0, c0, acc);
            }
        }
#pragma unroll
        for (int j = 0; j < 8; j++) {
            float s = 0.f;
#pragma unroll
            for (int i = 0; i < 8; i++) s = fmaf(acc[i][j], acc[i][j], s);
            col[j] += s;
        }
    }
#pragma unroll
    for (int j = 0; j < 8; j++) Pr[tid * 8 + j] = col[j];
    __syncthreads();
    if (tid < BS) {
        int txl = tid >> 3, j = tid & 7;
        float s = 0.f;
        for (int t = 0; t < 16; t++) s += Pr[(t * 16 + txl) * 8 + j];
        int mr = m0 + tid;
        out[(size_t)mr * NC + c] = -(0.9f * s + d_acc[(size_t)mr * NC + c]);
    }
}

// ---------------- launch ----------------
extern "C" void kernel_launch(void* const* d_in, const int* in_sizes, int n_in,
                              void* d_out, int out_size) {
    const float* X    = (const float*)d_in[0];
    const int*   y    = (const int*)  d_in[1];
    const float* Xq   = (const float*)d_in[2];
    const float* m    = (const float*)d_in[3];
    const float* kap  = (const float*)d_in[4];
    const float* nu   = (const float*)d_in[5];
    const float* diag = (const float*)d_in[6];
    const float* TL   = (const float*)d_in[7];
    float* out = (float*)d_out;
    (void)in_sizes; (void)n_in; (void)out_size;

    cudaFuncSetAttribute(k_chol_diag, cudaFuncAttributeMaxDynamicSharedMemorySize,
                         2 * 128 * 129 * 4);
    cudaFuncSetAttribute(k_trtri, cudaFuncAttributeMaxDynamicSharedMemorySize,
                         (128 * 129 + 2 * 32 * 129) * 4);

    k_count<<<1, 1024>>>(y);
    k_rank<<<16, 256>>>(y);
    k_scatter<<<NS, 256>>>(X);
    k_mu<<<dim3(D / 256, NC), 256>>>(m, kap);
    k_base<<<dim3(NB, NB), 256>>>(diag, TL, m, kap);
    k_sigma<<<dim3(NB, NB, NC), 256>>>(kap, nu);
    for (int kb = 0; kb < NB; kb++) {
        k_chol_diag<<<NC, 128, 2 * 128 * 129 * 4>>>(kb);
        if (kb < NB - 1) {
            k_panel<<<dim3(NB, NC), 256>>>(kb);
            k_syrk<<<dim3(NB, NB, NC), 256>>>(kb);
        }
    }
    for (int s = 1; s < NB; s++)
        k_trtri<<<dim3(NB, NC), 256, (128 * 129 + 2 * 32 * 129) * 4>>>(s);
    k_nd<<<dim3(MQ / 8, NC), 256>>>(Xq);
    k_sq<<<dim3(MQ / BS, NC), 256>>>(Xq, out);
}

// round 3
// speedup vs baseline: 1.3411x; 1.3411x over previous
#include <cuda_runtime.h>
#include <math.h>

#define D  1024
#define NC 16
#define NS 4096
#define MQ 4096
#define BS 128
#define NB 8

// ---------------- scratch (device globals: allocation-free contract) ----------------
__device__ float d_Xs[(size_t)NS * D];                // class-sorted X
__device__ int   d_counts[NC];
__device__ int   d_offsets[NC + 1];
__device__ int   d_dst[NS];
__device__ float d_mu[NC * D];
__device__ float d_base[(size_t)D * D];               // L L^T + kap m m^T (lower)
__device__ float d_sigma[(size_t)NC * D * D];         // sigma -> cholesky L (lower)
__device__ float d_invL[(size_t)NC * D * D];          // L^-1 (lower, upper zeroed)
__device__ float d_acc[(size_t)MQ * NC];              // 0.1 * ||diff||^2

// ---------------- small setup kernels ----------------
__global__ void k_count(const int* __restrict__ y) {
    __shared__ int cnt[NC];
    int t = threadIdx.x;
    if (t < NC) cnt[t] = 0;
    __syncthreads();
    for (int n = t; n < NS; n += blockDim.x) atomicAdd(&cnt[y[n]], 1);
    __syncthreads();
    if (t == 0) {
        int off = 0;
        for (int c = 0; c < NC; c++) { d_counts[c] = cnt[c]; d_offsets[c] = off; off += cnt[c]; }
        d_offsets[NC] = off;
    }
}

__global__ void k_rank(const int* __restrict__ y) {
    __shared__ int sy[NS];
    for (int i = threadIdx.x; i < NS; i += blockDim.x) sy[i] = y[i];
    __syncthreads();
    int n = blockIdx.x * blockDim.x + threadIdx.x;
    int c = sy[n];
    int r = 0;
    for (int p = 0; p < n; p++) r += (sy[p] == c);
    d_dst[n] = d_offsets[c] + r;
}

__global__ void k_scatter(const float* __restrict__ X) {
    int n = blockIdx.x;
    int dst = d_dst[n];
    const float* src = X + (size_t)n * D;
    float* dp = d_Xs + (size_t)dst * D;
    for (int j = threadIdx.x; j < D; j += blockDim.x) dp[j] = src[j];
}

__global__ void k_mu(const float* __restrict__ m, const float* __restrict__ kappa) {
    int c = blockIdx.y;
    int j = blockIdx.x * blockDim.x + threadIdx.x;
    int ks = d_offsets[c], ke = d_offsets[c + 1];
    float s = 0.f;
    for (int r = ks; r < ke; r++) s += d_Xs[(size_t)r * D + j];
    float kap = fabsf(*kappa) + 1e-6f;
    float Nj = (float)(ke - ks);
    d_mu[c * D + j] = (kap * m[j] + s) / (kap + Nj);
}

// ---------------- shared GEMM micro-kernel (128x128 tile, 256 thr, 8x8 micro) ----------------
__device__ __forceinline__ void mm32(const float* As, const float* Bs, int r0, int c0,
                                     float acc[8][8]) {
#pragma unroll 4
    for (int kk = 0; kk < 32; kk++) {
        float a[8], b[8];
#pragma unroll
        for (int u = 0; u < 8; u++) a[u] = As[kk * 129 + r0 + u];
#pragma unroll
        for (int u = 0; u < 8; u++) b[u] = Bs[kk * 129 + c0 + u];
#pragma unroll
        for (int i = 0; i < 8; i++)
#pragma unroll
            for (int j = 0; j < 8; j++) acc[i][j] = fmaf(a[i], b[j], acc[i][j]);
    }
}

__device__ __forceinline__ float Lval(const float* diag, const float* TL, int i, int k) {
    if (k < i) return TL[(size_t)i * D + k];
    if (k == i) return fabsf(diag[i]);
    return 0.f;
}

// base = L L^T + kap * m m^T  (lower tiles only)
__global__ void k_base(const float* __restrict__ diag, const float* __restrict__ TL,
                       const float* __restrict__ m, const float* __restrict__ kappa) {
    int bi = blockIdx.x, bj = blockIdx.y;
    if (bj > bi) return;
    __shared__ float As[32 * 129], Bs[32 * 129];
    int tid = threadIdx.x, tx = tid & 15, ty = tid >> 4;
    int r0 = ty * 8, c0 = tx * 8;
    float acc[8][8] = {};
    int kmax = (bj + 1) * BS;
    for (int kc = 0; kc < kmax; kc += 32) {
        __syncthreads();
#pragma unroll
        for (int l = 0; l < 16; l++) {
            int idx = tid + 256 * l;
            int i = idx >> 5, kk = idx & 31;
            As[kk * 129 + i] = Lval(diag, TL, bi * BS + i, kc + kk);
            Bs[kk * 129 + i] = Lval(diag, TL, bj * BS + i, kc + kk);
        }
        __syncthreads();
        mm32(As, Bs, r0, c0, acc);
    }
    float kap = fabsf(*kappa) + 1e-6f;
#pragma unroll
    for (int i = 0; i < 8; i++) {
        int gi = bi * BS + r0 + i;
#pragma unroll
        for (int j = 0; j < 8; j++) {
            int gj = bj * BS + c0 + j;
            if (gj <= gi)
                d_base[(size_t)gi * D + gj] = acc[i][j] + kap * m[gi] * m[gj];
        }
    }
}

// sigma[c] lower = (base + S_c - (kap+Nj) mu mu^T) / (nu_ + Nj + d + 2)
__global__ void k_sigma(const float* __restrict__ kappa, const float* __restrict__ nu) {
    int bi = blockIdx.x, bj = blockIdx.y, c = blockIdx.z;
    if (bj > bi) return;
    __shared__ float As[32 * 129], Bs[32 * 129];
    int tid = threadIdx.x, tx = tid & 15, ty = tid >> 4;
    int r0 = ty * 8, c0 = tx * 8;
    float acc[8][8] = {};
    int ks = d_offsets[c], ke = d_offsets[c + 1];
    for (int k0 = ks; k0 < ke; k0 += 32) {
        __syncthreads();
#pragma unroll
        for (int l = 0; l < 16; l++) {
            int idx = tid + 256 * l;
            int kk = idx >> 7, i = idx & 127;
            int krow = k0 + kk;
            float av = 0.f, bv = 0.f;
            if (krow < ke) {
                av = d_Xs[(size_t)krow * D + bi * BS + i];
                bv = d_Xs[(size_t)krow * D + bj * BS + i];
            }
            As[kk * 129 + i] = av;
            Bs[kk * 129 + i] = bv;
        }
        __syncthreads();
        mm32(As, Bs, r0, c0, acc);
    }
    float kap = fabsf(*kappa) + 1e-6f;
    float Nj = (float)(ke - ks);
    float nuv = fmaxf(*nu, (float)(D - 1) + 1e-6f);
    float invden = 1.f / (nuv + Nj + (float)D + 2.f);
    float coef = kap + Nj;
    float* Sg = d_sigma + (size_t)c * D * D;
#pragma unroll
    for (int i = 0; i < 8; i++) {
        int gi = bi * BS + r0 + i;
        float mi = d_mu[c * D + gi];
#pragma unroll
        for (int j = 0; j < 8; j++) {
            int gj = bj * BS + c0 + j;
            if (gj <= gi) {
                float mj = d_mu[c * D + gj];
                Sg[(size_t)gi * D + gj] =
                    (d_base[(size_t)gi * D + gj] + acc[i][j] - coef * mi * mj) * invden;
            }
        }
    }
}

// factor 128x128 diag block in smem; also produce its triangular inverse
__global__ void k_chol_diag(int kb) {
    extern __shared__ float sh[];
    float* A = sh;                 // 128 x 129
    float* V = sh + 128 * 129;     // 128 x 129
    int c = blockIdx.x;
    int t = threadIdx.x;           // 128 threads
    float* Sg = d_sigma + (size_t)c * D * D;
    for (int idx = t; idx < BS * BS; idx += BS) {
        int r = idx >> 7, col = idx & 127;
        A[r * 129 + col] = Sg[(size_t)(kb * BS + r) * D + kb * BS + col];
    }
    __syncthreads();
    for (int j = 0; j < BS; j++) {
        if (t == j) A[j * 129 + j] = sqrtf(A[j * 129 + j]);
        __syncthreads();
        float dj = A[j * 129 + j];
        if (t > j) A[t * 129 + j] /= dj;
        __syncthreads();
        if (t > j) {
            float l = A[t * 129 + j];
            for (int col = j + 1; col <= t; col++)
                A[t * 129 + col] -= l * A[col * 129 + j];
        }
        __syncthreads();
    }
    for (int idx = t; idx < BS * BS; idx += BS) {
        int r = idx >> 7, col = idx & 127;
        if (col <= r) Sg[(size_t)(kb * BS + r) * D + kb * BS + col] = A[r * 129 + col];
    }
    // forward substitution: thread t solves L z = e_t (column t of inverse)
    for (int r = 0; r < BS; r++) {
        float v;
        if (r < t) v = 0.f;
        else if (r == t) v = 1.f / A[r * 129 + r];
        else {
            float s = 0.f;
            for (int q = t; q < r; q++) s = fmaf(A[r * 129 + q], V[q * 129 + t], s);
            v = -s / A[r * 129 + r];
        }
        V[r * 129 + t] = v;
    }
    __syncthreads();
    float* iL = d_invL + (size_t)c * D * D;
    for (int idx = t; idx < BS * BS; idx += BS) {
        int r = idx >> 7, col = idx & 127;
        iL[(size_t)(kb * BS + r) * D + kb * BS + col] = (col <= r) ? V[r * 129 + col] : 0.f;
    }
}

// panel: L(bi,kb) = A(bi,kb) * invLkk^T
__global__ void k_panel(int kb) {
    int bi = blockIdx.x, c = blockIdx.y;
    if (bi <= kb) return;
    __shared__ float As[32 * 129], Bs[32 * 129];
    int tid = threadIdx.x, tx = tid & 15, ty = tid >> 4;
    int r0 = ty * 8, c0 = tx * 8;
    float acc[8][8] = {};
    float* Sg = d_sigma + (size_t)c * D * D;
    const float* iL = d_invL + (size_t)c * D * D;
    for (int kc = 0; kc < BS; kc += 32) {
        __syncthreads();
#pragma unroll
        for (int l = 0; l < 16; l++) {
            int idx = tid + 256 * l;
            int r = idx >> 5, kk = idx & 31;
            As[kk * 129 + r] = Sg[(size_t)(bi * BS + r) * D + kb * BS + kc + kk];
            Bs[kk * 129 + r] = iL[(size_t)(kb * BS + r) * D + kb * BS + kc + kk];
        }
        __syncthreads();
        mm32(As, Bs, r0, c0, acc);
    }
    __syncthreads();
#pragma unroll
    for (int i = 0; i < 8; i++)
#pragma unroll
        for (int j = 0; j < 8; j++)
            Sg[(size_t)(bi * BS + r0 + i) * D + kb * BS + c0 + j] = acc[i][j];
}

// trailing update: A(bi,bj) -= P_bi P_bj^T  for kb < bj <= bi
__global__ void k_syrk(int kb) {
    int bi = blockIdx.x, bj = blockIdx.y, c = blockIdx.z;
    if (bj <= kb || bj > bi) return;
    __shared__ float As[32 * 129], Bs[32 * 129];
    int tid = threadIdx.x, tx = tid & 15, ty = tid >> 4;
    int r0 = ty * 8, c0 = tx * 8;
    float acc[8][8] = {};
    float* Sg = d_sigma + (size_t)c * D * D;
    for (int kc = 0; kc < BS; kc += 32) {
        __syncthreads();
#pragma unroll
        for (int l = 0; l < 16; l++) {
            int idx = tid + 256 * l;
            int r = idx >> 5, kk = idx & 31;
            As[kk * 129 + r] = Sg[(size_t)(bi * BS + r) * D + kb * BS + kc + kk];
            Bs[kk * 129 + r] = Sg[(size_t)(bj * BS + r) * D + kb * BS + kc + kk];
        }
        __syncthreads();
        mm32(As, Bs, r0, c0, acc);
    }
    __syncthreads();
#pragma unroll
    for (int i = 0; i < 8; i++) {
        int gi = bi * BS + r0 + i;
#pragma unroll
        for (int j = 0; j < 8; j++) {
            int gj = bj * BS + c0 + j;
            if (bi != bj || gj <= gi)
                Sg[(size_t)gi * D + gj] -= acc[i][j];
        }
    }
}

// blocked trtri: invL(bi,bj) = -invL(bi,bi) * sum_{k=bj..bi-1} L(bi,k) invL(k,bj)
__global__ void k_trtri(int s) {
    int bj = blockIdx.x, c = blockIdx.y;
    if (bj + s >= NB) return;
    int bi = bj + s;
    extern __shared__ float sh[];
    float* Ts = sh;                    // 128 x 129
    float* As = sh + 128 * 129;        // 32 x 129
    float* Bs = As + 32 * 129;         // 32 x 129
    int tid = threadIdx.x, tx = tid & 15, ty = tid >> 4;
    int r0 = ty * 8, c0 = tx * 8;
    const float* Sg = d_sigma + (size_t)c * D * D;
    float* iL = d_invL + (size_t)c * D * D;
    float acc[8][8] = {};
    for (int kb = bj; kb < bi; kb++) {
        for (int kc = 0; kc < BS; kc += 32) {
            __syncthreads();
#pragma unroll
            for (int l = 0; l < 16; l++) {
                int idx = tid + 256 * l;
                {
                    int r = idx >> 5, kk = idx & 31;
                    As[kk * 129 + r] = Sg[(size_t)(bi * BS + r) * D + kb * BS + kc + kk];
                }
                {
                    int kk = idx >> 7, cc = idx & 127;
                    Bs[kk * 129 + cc] = iL[(size_t)(kb * BS + kc + kk) * D + bj * BS + cc];
                }
            }
            __syncthreads();
            mm32(As, Bs, r0, c0, acc);
        }
    }
    __syncthreads();
#pragma unroll
    for (int i = 0; i < 8; i++)
#pragma unroll
        for (int j = 0; j < 8; j++)
            Ts[(r0 + i) * 129 + c0 + j] = acc[i][j];
    __syncthreads();
    float a2[8][8] = {};
    for (int kc = 0; kc < BS; kc += 32) {
        __syncthreads();
#pragma unroll
        for (int l = 0; l < 16; l++) {
            int idx = tid + 256 * l;
            int r = idx >> 5, kk = idx & 31;
            As[kk * 129 + r] = iL[(size_t)(bi * BS + r) * D + bi * BS + kc + kk];
        }
        __syncthreads();
#pragma unroll 4
        for (int kk = 0; kk < 32; kk++) {
            float a[8], b[8];
#pragma unroll
            for (int u = 0; u < 8; u++) a[u] = As[kk * 129 + r0 + u];
#pragma unroll
            for (int u = 0; u < 8; u++) b[u] = Ts[(kc + kk) * 129 + c0 + u];
#pragma unroll
            for (int i = 0; i < 8; i++)
#pragma unroll
                for (int j = 0; j < 8; j++) a2[i][j] = fmaf(a[i], b[j], a2[i][j]);
        }
    }
#pragma unroll
    for (int i = 0; i < 8; i++)
#pragma unroll
        for (int j = 0; j < 8; j++)
            iL[(size_t)(bi * BS + r0 + i) * D + bj * BS + c0 + j] = -a2[i][j];
}

// 0.1 * ||xq - mu_c||^2  (exact fp32 part of the regularized quadratic form)
__global__ void k_nd(const float* __restrict__ Xq) {
    int c = blockIdx.y;
    int warp = threadIdx.x >> 5, lane = threadIdx.x & 31;
    int mr = blockIdx.x * 8 + warp;
    const float* xq = Xq + (size_t)mr * D;
    const float* mu = d_mu + c * D;
    float s = 0.f;
    for (int k = lane; k < D; k += 32) {
        float df = xq[k] - mu[k];
        s = fmaf(df, df, s);
    }
#pragma unroll
    for (int o = 16; o; o >>= 1) s += __shfl_xor_sync(0xffffffffu, s, o);
    if (!lane) d_acc[(size_t)mr * NC + c] = 0.1f * s;
}

// ---------------- TF32 tensor-core predict ----------------
__device__ __forceinline__ unsigned f2tf(float f) {
    unsigned u;
    asm("cvt.rna.tf32.f32 %0, %1;" : "=r"(u) : "f"(f));
    return u;
}

// main predict: col norms of Z = invL_c * (Xq - mu_c)^T via mma.sync tf32.
// Block = 128 queries x 1 class; 8 warps, each warp: 32 d-rows x 64 queries
// (2 m-tiles x 8 n-tiles of m16n8k8). Triangular K loop over row blocks bi.
__global__ void __launch_bounds__(256, 2) k_sq(const float* __restrict__ Xq,
                                               float* __restrict__ out) {
    int mb = blockIdx.x, c = blockIdx.y;
    int m0 = mb * BS;
    __shared__ unsigned Ws[128 * 33];   // invL tile  [row][k]
    __shared__ unsigned Ds[128 * 33];   // diff tile  [query][k]
    __shared__ float red[4][128];
    __shared__ float colAcc[128];
    int tid = threadIdx.x, lane = tid & 31, w = tid >> 5;
    int wr = w >> 1, wc = w & 1;
    const float* iL = d_invL + (size_t)c * D * D;
    const float* mu = d_mu + c * D;
    if (tid < 128) colAcc[tid] = 0.f;

    float cf[2][8][4];
    for (int bi = 0; bi < NB; bi++) {
#pragma unroll
        for (int mt = 0; mt < 2; mt++)
#pragma unroll
            for (int nt = 0; nt < 8; nt++)
#pragma unroll
                for (int r = 0; r < 4; r++) cf[mt][nt][r] = 0.f;

        for (int kt = 0; kt <= bi; kt++) {
            for (int kc = 0; kc < BS; kc += 32) {
                int k0 = kt * BS + kc;
                __syncthreads();
#pragma unroll
                for (int l = 0; l < 16; l++) {
                    int idx = tid + 256 * l;
                    int r = idx >> 5, kk = idx & 31;
                    Ws[r * 33 + kk] = f2tf(iL[(size_t)(bi * BS + r) * D + k0 + kk]);
                    Ds[r * 33 + kk] =
                        f2tf(Xq[(size_t)(m0 + r) * D + k0 + kk] - mu[k0 + kk]);
                }
                __syncthreads();
#pragma unroll
                for (int ks = 0; ks < 4; ks++) {
                    int kl = ks * 8;
                    unsigned a[2][4];
#pragma unroll
                    for (int mt = 0; mt < 2; mt++) {
                        int row = wr * 32 + mt * 16 + (lane >> 2);
                        int col = kl + (lane & 3);
                        a[mt][0] = Ws[row * 33 + col];
                        a[mt][1] = Ws[(row + 8) * 33 + col];
                        a[mt][2] = Ws[row * 33 + col + 4];
                        a[mt][3] = Ws[(row + 8) * 33 + col + 4];
                    }
#pragma unroll
                    for (int nt = 0; nt < 8; nt++) {
                        int q = wc * 64 + nt * 8 + (lane >> 2);
                        int kq = kl + (lane & 3);
                        unsigned b0 = Ds[q * 33 + kq];
                        unsigned b1 = Ds[q * 33 + kq + 4];
#pragma unroll
                        for (int mt = 0; mt < 2; mt++) {
                            asm volatile(
                                "mma.sync.aligned.m16n8k8.row.col.f32.tf32.tf32.f32 "
                                "{%0,%1,%2,%3},{%4,%5,%6,%7},{%8,%9},{%0,%1,%2,%3};"
                                : "+f"(cf[mt][nt][0]), "+f"(cf[mt][nt][1]),
                                  "+f"(cf[mt][nt][2]), "+f"(cf[mt][nt][3])
                                : "r"(a[mt][0]), "r"(a[mt][1]), "r"(a[mt][2]),
                                  "r"(a[mt][3]), "r"(b0), "r"(b1));
                        }
                    }
                }
            }
        }
        // square-accumulate Z tile into per-query sums.
        // c0/c1: col=(lane&3)*2 (+1), rows lane>>2 (+8 for c2/c3 at same cols).
        float qs[8][2];
#pragma unroll
        for (int nt = 0; nt < 8; nt++)
#pragma unroll
            for (int e = 0; e < 2; e++) {
                float s = 0.f;
#pragma unroll
                for (int mt = 0; mt < 2; mt++) {
                    float v0 = cf[mt][nt][e], v2 = cf[mt][nt][2 + e];
                    s = fmaf(v0, v0, s);
                    s = fmaf(v2, v2, s);
                }
                s += __shfl_xor_sync(0xffffffffu, s, 4);
                s += __shfl_xor_sync(0xffffffffu, s, 8);
                s += __shfl_xor_sync(0xffffffffu, s, 16);
                qs[nt][e] = s;
            }
        __syncthreads();
        if ((lane >> 2) == 0) {
#pragma unroll
            for (int nt = 0; nt < 8; nt++)
#pragma unroll
                for (int e = 0; e < 2; e++) {
                    int q = wc * 64 + nt * 8 + (lane & 3) * 2 + e;
                    red[wr][q] = qs[nt][e];
                }
        }
        __syncthreads();
        if (tid < 128)
            colAcc[tid] += red[0][tid] + red[1][tid] + red[2][tid] + red[3][tid];
    }
    __syncthreads();
    if (tid < 128) {
        int mr = m0 + tid;
        out[(size_t)mr * NC + c] = -(0.9f * colAcc[tid] + d_acc[(size_t)mr * NC + c]);
    }
}

// ---------------- launch ----------------
extern "C" void kernel_launch(void* const* d_in, const int* in_sizes, int n_in,
                              void* d_out, int out_size) {
    const float* X    = (const float*)d_in[0];
    const int*   y    = (const int*)  d_in[1];
    const float* Xq   = (const float*)d_in[2];
    const float* m    = (const float*)d_in[3];
    const float* kap  = (const float*)d_in[4];
    const float* nu   = (const float*)d_in[5];
    const float* diag = (const float*)d_in[6];
    const float* TL   = (const float*)d_in[7];
    float* out = (float*)d_out;
    (void)in_sizes; (void)n_in; (void)out_size;

    cudaFuncSetAttribute(k_chol_diag, cudaFuncAttributeMaxDynamicSharedMemorySize,
                         2 * 128 * 129 * 4);
    cudaFuncSetAttribute(k_trtri, cudaFuncAttributeMaxDynamicSharedMemorySize,
                         (128 * 129 + 2 * 32 * 129) * 4);

    k_count<<<1, 1024>>>(y);
    k_rank<<<16, 256>>>(y);
    k_scatter<<<NS, 256>>>(X);
    k_mu<<<dim3(D / 256, NC), 256>>>(m, kap);
    k_base<<<dim3(NB, NB), 256>>>(diag, TL, m, kap);
    k_sigma<<<dim3(NB, NB, NC), 256>>>(kap, nu);
    for (int kb = 0; kb < NB; kb++) {
        k_chol_diag<<<NC, 128, 2 * 128 * 129 * 4>>>(kb);
        if (kb < NB - 1) {
            k_panel<<<dim3(NB, NC), 256>>>(kb);
            k_syrk<<<dim3(NB, NB, NC), 256>>>(kb);
        }
    }
    for (int s = 1; s < NB; s++)
        k_trtri<<<dim3(NB, NC), 256, (128 * 129 + 2 * 32 * 129) * 4>>>(s);
    k_nd<<<dim3(MQ / 8, NC), 256>>>(Xq);
    k_sq<<<dim3(MQ / BS, NC), 256>>>(Xq, out);
}

// round 6
// speedup vs baseline: 1.3467x; 1.0042x over previous
#include <cuda_runtime.h>
#include <math.h>

#define D  1024
#define NC 16
#define NS 4096
#define MQ 4096
#define BS 128
#define NB 8

// ---------------- scratch (device globals: allocation-free contract) ----------------
__device__ float d_Xs[(size_t)NS * D];                // class-sorted X
__device__ int   d_counts[NC];
__device__ int   d_offsets[NC + 1];
__device__ int   d_dst[NS];
__device__ float d_mu[NC * D];
__device__ float d_base[(size_t)D * D];               // L L^T + kap m m^T (lower)
__device__ float d_sigma[(size_t)NC * D * D];         // sigma -> cholesky L (lower)
__device__ float d_invL[(size_t)NC * D * D];          // L^-1 (lower, upper zeroed)
__device__ float d_acc[(size_t)MQ * NC];              // 0.1 * ||diff||^2

// ---------------- small setup kernels ----------------
__global__ void k_count(const int* __restrict__ y) {
    __shared__ int cnt[NC];
    int t = threadIdx.x;
    if (t < NC) cnt[t] = 0;
    __syncthreads();
    for (int n = t; n < NS; n += blockDim.x) atomicAdd(&cnt[y[n]], 1);
    __syncthreads();
    if (t == 0) {
        int off = 0;
        for (int c = 0; c < NC; c++) { d_counts[c] = cnt[c]; d_offsets[c] = off; off += cnt[c]; }
        d_offsets[NC] = off;
    }
}

__global__ void k_rank(const int* __restrict__ y) {
    __shared__ int sy[NS];
    for (int i = threadIdx.x; i < NS; i += blockDim.x) sy[i] = y[i];
    __syncthreads();
    int n = blockIdx.x * blockDim.x + threadIdx.x;
    int c = sy[n];
    int r = 0;
    for (int p = 0; p < n; p++) r += (sy[p] == c);
    d_dst[n] = d_offsets[c] + r;
}

__global__ void k_scatter(const float* __restrict__ X) {
    int n = blockIdx.x;
    int dst = d_dst[n];
    const float* src = X + (size_t)n * D;
    float* dp = d_Xs + (size_t)dst * D;
    for (int j = threadIdx.x; j < D; j += blockDim.x) dp[j] = src[j];
}

__global__ void k_mu(const float* __restrict__ m, const float* __restrict__ kappa) {
    int c = blockIdx.y;
    int j = blockIdx.x * blockDim.x + threadIdx.x;
    int ks = d_offsets[c], ke = d_offsets[c + 1];
    float s = 0.f;
    for (int r = ks; r < ke; r++) s += d_Xs[(size_t)r * D + j];
    float kap = fabsf(*kappa) + 1e-6f;
    float Nj = (float)(ke - ks);
    d_mu[c * D + j] = (kap * m[j] + s) / (kap + Nj);
}

// ---------------- shared GEMM micro-kernel (128x128 tile, 256 thr, 8x8 micro) ----------------
__device__ __forceinline__ void mm32(const float* As, const float* Bs, int r0, int c0,
                                     float acc[8][8]) {
#pragma unroll 4
    for (int kk = 0; kk < 32; kk++) {
        float a[8], b[8];
#pragma unroll
        for (int u = 0; u < 8; u++) a[u] = As[kk * 129 + r0 + u];
#pragma unroll
        for (int u = 0; u < 8; u++) b[u] = Bs[kk * 129 + c0 + u];
#pragma unroll
        for (int i = 0; i < 8; i++)
#pragma unroll
            for (int j = 0; j < 8; j++) acc[i][j] = fmaf(a[i], b[j], acc[i][j]);
    }
}

__device__ __forceinline__ float Lval(const float* diag, const float* TL, int i, int k) {
    if (k < i) return TL[(size_t)i * D + k];
    if (k == i) return fabsf(diag[i]);
    return 0.f;
}

// base = L L^T + kap * m m^T  (lower tiles only)
__global__ void k_base(const float* __restrict__ diag, const float* __restrict__ TL,
                       const float* __restrict__ m, const float* __restrict__ kappa) {
    int bi = blockIdx.x, bj = blockIdx.y;
    if (bj > bi) return;
    __shared__ float As[32 * 129], Bs[32 * 129];
    int tid = threadIdx.x, tx = tid & 15, ty = tid >> 4;
    int r0 = ty * 8, c0 = tx * 8;
    float acc[8][8] = {};
    int kmax = (bj + 1) * BS;
    for (int kc = 0; kc < kmax; kc += 32) {
        __syncthreads();
#pragma unroll
        for (int l = 0; l < 16; l++) {
            int idx = tid + 256 * l;
            int i = idx >> 5, kk = idx & 31;
            As[kk * 129 + i] = Lval(diag, TL, bi * BS + i, kc + kk);
            Bs[kk * 129 + i] = Lval(diag, TL, bj * BS + i, kc + kk);
        }
        __syncthreads();
        mm32(As, Bs, r0, c0, acc);
    }
    float kap = fabsf(*kappa) + 1e-6f;
#pragma unroll
    for (int i = 0; i < 8; i++) {
        int gi = bi * BS + r0 + i;
#pragma unroll
        for (int j = 0; j < 8; j++) {
            int gj = bj * BS + c0 + j;
            if (gj <= gi)
                d_base[(size_t)gi * D + gj] = acc[i][j] + kap * m[gi] * m[gj];
        }
    }
}

// sigma[c] lower = (base + S_c - (kap+Nj) mu mu^T) / (nu_ + Nj + d + 2)
__global__ void k_sigma(const float* __restrict__ kappa, const float* __restrict__ nu) {
    int bi = blockIdx.x, bj = blockIdx.y, c = blockIdx.z;
    if (bj > bi) return;
    __shared__ float As[32 * 129], Bs[32 * 129];
    int tid = threadIdx.x, tx = tid & 15, ty = tid >> 4;
    int r0 = ty * 8, c0 = tx * 8;
    float acc[8][8] = {};
    int ks = d_offsets[c], ke = d_offsets[c + 1];
    for (int k0 = ks; k0 < ke; k0 += 32) {
        __syncthreads();
#pragma unroll
        for (int l = 0; l < 16; l++) {
            int idx = tid + 256 * l;
            int kk = idx >> 7, i = idx & 127;
            int krow = k0 + kk;
            float av = 0.f, bv = 0.f;
            if (krow < ke) {
                av = d_Xs[(size_t)krow * D + bi * BS + i];
                bv = d_Xs[(size_t)krow * D + bj * BS + i];
            }
            As[kk * 129 + i] = av;
            Bs[kk * 129 + i] = bv;
        }
        __syncthreads();
        mm32(As, Bs, r0, c0, acc);
    }
    float kap = fabsf(*kappa) + 1e-6f;
    float Nj = (float)(ke - ks);
    float nuv = fmaxf(*nu, (float)(D - 1) + 1e-6f);
    float invden = 1.f / (nuv + Nj + (float)D + 2.f);
    float coef = kap + Nj;
    float* Sg = d_sigma + (size_t)c * D * D;
#pragma unroll
    for (int i = 0; i < 8; i++) {
        int gi = bi * BS + r0 + i;
        float mi = d_mu[c * D + gi];
#pragma unroll
        for (int j = 0; j < 8; j++) {
            int gj = bj * BS + c0 + j;
            if (gj <= gi) {
                float mj = d_mu[c * D + gj];
                Sg[(size_t)gi * D + gj] =
                    (d_base[(size_t)gi * D + gj] + acc[i][j] - coef * mi * mj) * invden;
            }
        }
    }
}

// factor 128x128 diag block in smem; also produce its triangular inverse
__global__ void k_chol_diag(int kb) {
    extern __shared__ float sh[];
    float* A = sh;                 // 128 x 129
    float* V = sh + 128 * 129;     // 128 x 129
    int c = blockIdx.x;
    int t = threadIdx.x;           // 128 threads
    float* Sg = d_sigma + (size_t)c * D * D;
    for (int idx = t; idx < BS * BS; idx += BS) {
        int r = idx >> 7, col = idx & 127;
        A[r * 129 + col] = Sg[(size_t)(kb * BS + r) * D + kb * BS + col];
    }
    __syncthreads();
    for (int j = 0; j < BS; j++) {
        if (t == j) A[j * 129 + j] = sqrtf(A[j * 129 + j]);
        __syncthreads();
        float dj = A[j * 129 + j];
        if (t > j) A[t * 129 + j] /= dj;
        __syncthreads();
        if (t > j) {
            float l = A[t * 129 + j];
            for (int col = j + 1; col <= t; col++)
                A[t * 129 + col] -= l * A[col * 129 + j];
        }
        __syncthreads();
    }
    for (int idx = t; idx < BS * BS; idx += BS) {
        int r = idx >> 7, col = idx & 127;
        if (col <= r) Sg[(size_t)(kb * BS + r) * D + kb * BS + col] = A[r * 129 + col];
    }
    // forward substitution: thread t solves L z = e_t (column t of inverse)
    for (int r = 0; r < BS; r++) {
        float v;
        if (r < t) v = 0.f;
        else if (r == t) v = 1.f / A[r * 129 + r];
        else {
            float s = 0.f;
            for (int q = t; q < r; q++) s = fmaf(A[r * 129 + q], V[q * 129 + t], s);
            v = -s / A[r * 129 + r];
        }
        V[r * 129 + t] = v;
    }
    __syncthreads();
    float* iL = d_invL + (size_t)c * D * D;
    for (int idx = t; idx < BS * BS; idx += BS) {
        int r = idx >> 7, col = idx & 127;
        iL[(size_t)(kb * BS + r) * D + kb * BS + col] = (col <= r) ? V[r * 129 + col] : 0.f;
    }
}

// panel: L(bi,kb) = A(bi,kb) * invLkk^T
__global__ void k_panel(int kb) {
    int bi = blockIdx.x, c = blockIdx.y;
    if (bi <= kb) return;
    __shared__ float As[32 * 129], Bs[32 * 129];
    int tid = threadIdx.x, tx = tid & 15, ty = tid >> 4;
    int r0 = ty * 8, c0 = tx * 8;
    float acc[8][8] = {};
    float* Sg = d_sigma + (size_t)c * D * D;
    const float* iL = d_invL + (size_t)c * D * D;
    for (int kc = 0; kc < BS; kc += 32) {
        __syncthreads();
#pragma unroll
        for (int l = 0; l < 16; l++) {
            int idx = tid + 256 * l;
            int r = idx >> 5, kk = idx & 31;
            As[kk * 129 + r] = Sg[(size_t)(bi * BS + r) * D + kb * BS + kc + kk];
            Bs[kk * 129 + r] = iL[(size_t)(kb * BS + r) * D + kb * BS + kc + kk];
        }
        __syncthreads();
        mm32(As, Bs, r0, c0, acc);
    }
    __syncthreads();
#pragma unroll
    for (int i = 0; i < 8; i++)
#pragma unroll
        for (int j = 0; j < 8; j++)
            Sg[(size_t)(bi * BS + r0 + i) * D + kb * BS + c0 + j] = acc[i][j];
}

// trailing update: A(bi,bj) -= P_bi P_bj^T  for kb < bj <= bi
__global__ void k_syrk(int kb) {
    int bi = blockIdx.x, bj = blockIdx.y, c = blockIdx.z;
    if (bj <= kb || bj > bi) return;
    __shared__ float As[32 * 129], Bs[32 * 129];
    int tid = threadIdx.x, tx = tid & 15, ty = tid >> 4;
    int r0 = ty * 8, c0 = tx * 8;
    float acc[8][8] = {};
    float* Sg = d_sigma + (size_t)c * D * D;
    for (int kc = 0; kc < BS; kc += 32) {
        __syncthreads();
#pragma unroll
        for (int l = 0; l < 16; l++) {
            int idx = tid + 256 * l;
            int r = idx >> 5, kk = idx & 31;
            As[kk * 129 + r] = Sg[(size_t)(bi * BS + r) * D + kb * BS + kc + kk];
            Bs[kk * 129 + r] = Sg[(size_t)(bj * BS + r) * D + kb * BS + kc + kk];
        }
        __syncthreads();
        mm32(As, Bs, r0, c0, acc);
    }
    __syncthreads();
#pragma unroll
    for (int i = 0; i < 8; i++) {
        int gi = bi * BS + r0 + i;
#pragma unroll
        for (int j = 0; j < 8; j++) {
            int gj = bj * BS + c0 + j;
            if (bi != bj || gj <= gi)
                Sg[(size_t)gi * D + gj] -= acc[i][j];
        }
    }
}

// blocked trtri: invL(bi,bj) = -invL(bi,bi) * sum_{k=bj..bi-1} L(bi,k) invL(k,bj)
__global__ void k_trtri(int s) {
    int bj = blockIdx.x, c = blockIdx.y;
    if (bj + s >= NB) return;
    int bi = bj + s;
    extern __shared__ float sh[];
    float* Ts = sh;                    // 128 x 129
    float* As = sh + 128 * 129;        // 32 x 129
    float* Bs = As + 32 * 129;         // 32 x 129
    int tid = threadIdx.x, tx = tid & 15, ty = tid >> 4;
    int r0 = ty * 8, c0 = tx * 8;
    const float* Sg = d_sigma + (size_t)c * D * D;
    float* iL = d_invL + (size_t)c * D * D;
    float acc[8][8] = {};
    for (int kb = bj; kb < bi; kb++) {
        for (int kc = 0; kc < BS; kc += 32) {
            __syncthreads();
#pragma unroll
            for (int l = 0; l < 16; l++) {
                int idx = tid + 256 * l;
                {
                    int r = idx >> 5, kk = idx & 31;
                    As[kk * 129 + r] = Sg[(size_t)(bi * BS + r) * D + kb * BS + kc + kk];
                }
                {
                    int kk = idx >> 7, cc = idx & 127;
                    Bs[kk * 129 + cc] = iL[(size_t)(kb * BS + kc + kk) * D + bj * BS + cc];
                }
            }
            __syncthreads();
            mm32(As, Bs, r0, c0, acc);
        }
    }
    __syncthreads();
#pragma unroll
    for (int i = 0; i < 8; i++)
#pragma unroll
        for (int j = 0; j < 8; j++)
            Ts[(r0 + i) * 129 + c0 + j] = acc[i][j];
    __syncthreads();
    float a2[8][8] = {};
    for (int kc = 0; kc < BS; kc += 32) {
        __syncthreads();
#pragma unroll
        for (int l = 0; l < 16; l++) {
            int idx = tid + 256 * l;
            int r = idx >> 5, kk = idx & 31;
            As[kk * 129 + r] = iL[(size_t)(bi * BS + r) * D + bi * BS + kc + kk];
        }
        __syncthreads();
#pragma unroll 4
        for (int kk = 0; kk < 32; kk++) {
            float a[8], b[8];
#pragma unroll
            for (int u = 0; u < 8; u++) a[u] = As[kk * 129 + r0 + u];
#pragma unroll
            for (int u = 0; u < 8; u++) b[u] = Ts[(kc + kk) * 129 + c0 + u];
#pragma unroll
            for (int i = 0; i < 8; i++)
#pragma unroll
                for (int j = 0; j < 8; j++) a2[i][j] = fmaf(a[i], b[j], a2[i][j]);
        }
    }
#pragma unroll
    for (int i = 0; i < 8; i++)
#pragma unroll
        for (int j = 0; j < 8; j++)
            iL[(size_t)(bi * BS + r0 + i) * D + bj * BS + c0 + j] = -a2[i][j];
}

// 0.1 * ||xq - mu_c||^2  (exact fp32 part of the regularized quadratic form)
__global__ void k_nd(const float* __restrict__ Xq) {
    int c = blockIdx.y;
    int warp = threadIdx.x >> 5, lane = threadIdx.x & 31;
    int mr = blockIdx.x * 8 + warp;
    const float* xq = Xq + (size_t)mr * D;
    const float* mu = d_mu + c * D;
    float s = 0.f;
    for (int k = lane; k < D; k += 32) {
        float df = xq[k] - mu[k];
        s = fmaf(df, df, s);
    }
#pragma unroll
    for (int o = 16; o; o >>= 1) s += __shfl_xor_sync(0xffffffffu, s, o);
    if (!lane) d_acc[(size_t)mr * NC + c] = 0.1f * s;
}

// ---------------- TF32 tensor-core predict ----------------
__device__ __forceinline__ unsigned f2tf(float f) {
    unsigned u;
    asm("cvt.rna.tf32.f32 %0, %1;" : "=r"(u) : "f"(f));
    return u;
}

// main predict: col norms of Z = invL_c * (Xq - mu_c)^T via mma.sync tf32.
// Block = 128 queries x 1 class; 8 warps, each warp: 32 d-rows x 64 queries
// (2 m-tiles x 8 n-tiles of m16n8k8). Triangular K loop over row blocks bi.
__global__ void __launch_bounds__(256, 2) k_sq(const float* __restrict__ Xq,
                                               float* __restrict__ out) {
    int mb = blockIdx.x, c = blockIdx.y;
    int m0 = mb * BS;
    __shared__ unsigned Ws[128 * 33];   // invL tile  [row][k]
    __shared__ unsigned Ds[128 * 33];   // diff tile  [query][k]
    __shared__ float red[4][128];
    __shared__ float colAcc[128];
    int tid = threadIdx.x, lane = tid & 31, w = tid >> 5;
    int wr = w >> 1, wc = w & 1;
    const float* iL = d_invL + (size_t)c * D * D;
    const float* mu = d_mu + c * D;
    if (tid < 128) colAcc[tid] = 0.f;

    float cf[2][8][4];
    for (int bi = 0; bi < NB; bi++) {
#pragma unroll
        for (int mt = 0; mt < 2; mt++)
#pragma unroll
            for (int nt = 0; nt < 8; nt++)
#pragma unroll
                for (int r = 0; r < 4; r++) cf[mt][nt][r] = 0.f;

        for (int kt = 0; kt <= bi; kt++) {
            for (int kc = 0; kc < BS; kc += 32) {
                int k0 = kt * BS + kc;
                __syncthreads();
#pragma unroll
                for (int l = 0; l < 16; l++) {
                    int idx = tid + 256 * l;
                    int r = idx >> 5, kk = idx & 31;
                    Ws[r * 33 + kk] = f2tf(iL[(size_t)(bi * BS + r) * D + k0 + kk]);
                    Ds[r * 33 + kk] =
                        f2tf(Xq[(size_t)(m0 + r) * D + k0 + kk] - mu[k0 + kk]);
                }
                __syncthreads();
#pragma unroll
                for (int ks = 0; ks < 4; ks++) {
                    int kl = ks * 8;
                    unsigned a[2][4];
#pragma unroll
                    for (int mt = 0; mt < 2; mt++) {
                        int row = wr * 32 + mt * 16 + (lane >> 2);
                        int col = kl + (lane & 3);
                        a[mt][0] = Ws[row * 33 + col];
                        a[mt][1] = Ws[(row + 8) * 33 + col];
                        a[mt][2] = Ws[row * 33 + col + 4];
                        a[mt][3] = Ws[(row + 8) * 33 + col + 4];
                    }
#pragma unroll
                    for (int nt = 0; nt < 8; nt++) {
                        int q = wc * 64 + nt * 8 + (lane >> 2);
                        int kq = kl + (lane & 3);
                        unsigned b0 = Ds[q * 33 + kq];
                        unsigned b1 = Ds[q * 33 + kq + 4];
#pragma unroll
                        for (int mt = 0; mt < 2; mt++) {
                            asm volatile(
                                "mma.sync.aligned.m16n8k8.row.col.f32.tf32.tf32.f32 "
                                "{%0,%1,%2,%3},{%4,%5,%6,%7},{%8,%9},{%0,%1,%2,%3};"
                                : "+f"(cf[mt][nt][0]), "+f"(cf[mt][nt][1]),
                                  "+f"(cf[mt][nt][2]), "+f"(cf[mt][nt][3])
                                : "r"(a[mt][0]), "r"(a[mt][1]), "r"(a[mt][2]),
                                  "r"(a[mt][3]), "r"(b0), "r"(b1));
                        }
                    }
                }
            }
        }
        // square-accumulate Z tile into per-query sums.
        // c0/c1: col=(lane&3)*2 (+1), rows lane>>2 (+8 for c2/c3 at same cols).
        float qs[8][2];
#pragma unroll
        for (int nt = 0; nt < 8; nt++)
#pragma unroll
            for (int e = 0; e < 2; e++) {
                float s = 0.f;
#pragma unroll
                for (int mt = 0; mt < 2; mt++) {
                    float v0 = cf[mt][nt][e], v2 = cf[mt][nt][2 + e];
                    s = fmaf(v0, v0, s);
                    s = fmaf(v2, v2, s);
                }
                s += __shfl_xor_sync(0xffffffffu, s, 4);
                s += __shfl_xor_sync(0xffffffffu, s, 8);
                s += __shfl_xor_sync(0xffffffffu, s, 16);
                qs[nt][e] = s;
            }
        __syncthreads();
        if ((lane >> 2) == 0) {
#pragma unroll
            for (int nt = 0; nt < 8; nt++)
#pragma unroll
                for (int e = 0; e < 2; e++) {
                    int q = wc * 64 + nt * 8 + (lane & 3) * 2 + e;
                    red[wr][q] = qs[nt][e];
                }
        }
        __syncthreads();
        if (tid < 128)
            colAcc[tid] += red[0][tid] + red[1][tid] + red[2][tid] + red[3][tid];
    }
    __syncthreads();
    if (tid < 128) {
        int mr = m0 + tid;
        out[(size_t)mr * NC + c] = -(0.9f * colAcc[tid] + d_acc[(size_t)mr * NC + c]);
    }
}

// ---------------- launch ----------------
extern "C" void kernel_launch(void* const* d_in, const int* in_sizes, int n_in,
                              void* d_out, int out_size) {
    const float* X    = (const float*)d_in[0];
    const int*   y    = (const int*)  d_in[1];
    const float* Xq   = (const float*)d_in[2];
    const float* m    = (const float*)d_in[3];
    const float* kap  = (const float*)d_in[4];
    const float* nu   = (const float*)d_in[5];
    const float* diag = (const float*)d_in[6];
    const float* TL   = (const float*)d_in[7];
    float* out = (float*)d_out;
    (void)in_sizes; (void)n_in; (void)out_size;

    cudaFuncSetAttribute(k_chol_diag, cudaFuncAttributeMaxDynamicSharedMemorySize,
                         2 * 128 * 129 * 4);
    cudaFuncSetAttribute(k_trtri, cudaFuncAttributeMaxDynamicSharedMemorySize,
                         (128 * 129 + 2 * 32 * 129) * 4);

    k_count<<<1, 1024>>>(y);
    k_rank<<<16, 256>>>(y);
    k_scatter<<<NS, 256>>>(X);
    k_mu<<<dim3(D / 256, NC), 256>>>(m, kap);
    k_base<<<dim3(NB, NB), 256>>>(diag, TL, m, kap);
    k_sigma<<<dim3(NB, NB, NC), 256>>>(kap, nu);
    for (int kb = 0; kb < NB; kb++) {
        k_chol_diag<<<NC, 128, 2 * 128 * 129 * 4>>>(kb);
        if (kb < NB - 1) {
            k_panel<<<dim3(NB, NC), 256>>>(kb);
            k_syrk<<<dim3(NB, NB, NC), 256>>>(kb);
        }
    }
    for (int s = 1; s < NB; s++)
        k_trtri<<<dim3(NB, NC), 256, (128 * 129 + 2 * 32 * 129) * 4>>>(s);
    k_nd<<<dim3(MQ / 8, NC), 256>>>(Xq);
    k_sq<<<dim3(MQ / BS, NC), 256>>>(Xq, out);
}

// round 9
// speedup vs baseline: 1.8623x; 1.3828x over previous
#include <cuda_runtime.h>
#include <math.h>

#define D  1024
#define NC 16
#define NS 4096
#define MQ 4096
#define BS 128
#define NB 8

// ---------------- scratch (device globals: allocation-free contract) ----------------
__device__ float d_Xs[(size_t)NS * D];
__device__ int   d_counts[NC];
__device__ int   d_offsets[NC + 1];
__device__ int   d_dst[NS];
__device__ float d_mu[NC * D];
__device__ float d_base[(size_t)D * D];
__device__ float d_sigma[(size_t)NC * D * D];   // sigma -> cholesky L (lower)
__device__ float d_invL[(size_t)NC * D * D];    // L^-1 (lower, upper zeroed)
__device__ float d_acc[(size_t)MQ * NC];
__device__ float d_T[(size_t)NC * 512 * 512];   // recursive-doubling scratch

// ---------------- small setup kernels ----------------
__global__ void k_count(const int* __restrict__ y) {
    __shared__ int cnt[NC];
    int t = threadIdx.x;
    if (t < NC) cnt[t] = 0;
    __syncthreads();
    for (int n = t; n < NS; n += blockDim.x) atomicAdd(&cnt[y[n]], 1);
    __syncthreads();
    if (t == 0) {
        int off = 0;
        for (int c = 0; c < NC; c++) { d_counts[c] = cnt[c]; d_offsets[c] = off; off += cnt[c]; }
        d_offsets[NC] = off;
    }
}

__global__ void k_rank(const int* __restrict__ y) {
    __shared__ int sy[NS];
    for (int i = threadIdx.x; i < NS; i += blockDim.x) sy[i] = y[i];
    __syncthreads();
    int n = blockIdx.x * blockDim.x + threadIdx.x;
    int c = sy[n];
    int r = 0;
    for (int p = 0; p < n; p++) r += (sy[p] == c);
    d_dst[n] = d_offsets[c] + r;
}

__global__ void k_scatter(const float* __restrict__ X) {
    int n = blockIdx.x;
    int dst = d_dst[n];
    const float* src = X + (size_t)n * D;
    float* dp = d_Xs + (size_t)dst * D;
    for (int j = threadIdx.x; j < D; j += blockDim.x) dp[j] = src[j];
}

__global__ void k_mu(const float* __restrict__ m, const float* __restrict__ kappa) {
    int c = blockIdx.y;
    int j = blockIdx.x * blockDim.x + threadIdx.x;
    int ks = d_offsets[c], ke = d_offsets[c + 1];
    float s = 0.f;
    for (int r = ks; r < ke; r++) s += d_Xs[(size_t)r * D + j];
    float kap = fabsf(*kappa) + 1e-6f;
    float Nj = (float)(ke - ks);
    d_mu[c * D + j] = (kap * m[j] + s) / (kap + Nj);
}

// ---------------- shared GEMM micro-kernel ----------------
__device__ __forceinline__ void mm32(const float* As, const float* Bs, int r0, int c0,
                                     float acc[8][8]) {
#pragma unroll 4
    for (int kk = 0; kk < 32; kk++) {
        float a[8], b[8];
#pragma unroll
        for (int u = 0; u < 8; u++) a[u] = As[kk * 129 + r0 + u];
#pragma unroll
        for (int u = 0; u < 8; u++) b[u] = Bs[kk * 129 + c0 + u];
#pragma unroll
        for (int i = 0; i < 8; i++)
#pragma unroll
            for (int j = 0; j < 8; j++) acc[i][j] = fmaf(a[i], b[j], acc[i][j]);
    }
}

__device__ __forceinline__ float Lval(const float* diag, const float* TL, int i, int k) {
    if (k < i) return TL[(size_t)i * D + k];
    if (k == i) return fabsf(diag[i]);
    return 0.f;
}

// base = L L^T + kap * m m^T  (lower tiles only)
__global__ void k_base(const float* __restrict__ diag, const float* __restrict__ TL,
                       const float* __restrict__ m, const float* __restrict__ kappa) {
    int bi = blockIdx.x, bj = blockIdx.y;
    if (bj > bi) return;
    __shared__ float As[32 * 129], Bs[32 * 129];
    int tid = threadIdx.x, tx = tid & 15, ty = tid >> 4;
    int r0 = ty * 8, c0 = tx * 8;
    float acc[8][8] = {};
    int kmax = (bj + 1) * BS;
    for (int kc = 0; kc < kmax; kc += 32) {
        __syncthreads();
#pragma unroll
        for (int l = 0; l < 16; l++) {
            int idx = tid + 256 * l;
            int i = idx >> 5, kk = idx & 31;
            As[kk * 129 + i] = Lval(diag, TL, bi * BS + i, kc + kk);
            Bs[kk * 129 + i] = Lval(diag, TL, bj * BS + i, kc + kk);
        }
        __syncthreads();
        mm32(As, Bs, r0, c0, acc);
    }
    float kap = fabsf(*kappa) + 1e-6f;
#pragma unroll
    for (int i = 0; i < 8; i++) {
        int gi = bi * BS + r0 + i;
#pragma unroll
        for (int j = 0; j < 8; j++) {
            int gj = bj * BS + c0 + j;
            if (gj <= gi)
                d_base[(size_t)gi * D + gj] = acc[i][j] + kap * m[gi] * m[gj];
        }
    }
}

// sigma[c] lower = (base + S_c - (kap+Nj) mu mu^T) / (nu_ + Nj + d + 2)
__global__ void k_sigma(const float* __restrict__ kappa, const float* __restrict__ nu) {
    int bi = blockIdx.x, bj = blockIdx.y, c = blockIdx.z;
    if (bj > bi) return;
    __shared__ float As[32 * 129], Bs[32 * 129];
    int tid = threadIdx.x, tx = tid & 15, ty = tid >> 4;
    int r0 = ty * 8, c0 = tx * 8;
    float acc[8][8] = {};
    int ks = d_offsets[c], ke = d_offsets[c + 1];
    for (int k0 = ks; k0 < ke; k0 += 32) {
        __syncthreads();
#pragma unroll
        for (int l = 0; l < 16; l++) {
            int idx = tid + 256 * l;
            int kk = idx >> 7, i = idx & 127;
            int krow = k0 + kk;
            float av = 0.f, bv = 0.f;
            if (krow < ke) {
                av = d_Xs[(size_t)krow * D + bi * BS + i];
                bv = d_Xs[(size_t)krow * D + bj * BS + i];
            }
            As[kk * 129 + i] = av;
            Bs[kk * 129 + i] = bv;
        }
        __syncthreads();
        mm32(As, Bs, r0, c0, acc);
    }
    float kap = fabsf(*kappa) + 1e-6f;
    float Nj = (float)(ke - ks);
    float nuv = fmaxf(*nu, (float)(D - 1) + 1e-6f);
    float invden = 1.f / (nuv + Nj + (float)D + 2.f);
    float coef = kap + Nj;
    float* Sg = d_sigma + (size_t)c * D * D;
#pragma unroll
    for (int i = 0; i < 8; i++) {
        int gi = bi * BS + r0 + i;
        float mi = d_mu[c * D + gi];
#pragma unroll
        for (int j = 0; j < 8; j++) {
            int gj = bj * BS + c0 + j;
            if (gj <= gi) {
                float mj = d_mu[c * D + gj];
                Sg[(size_t)gi * D + gj] =
                    (d_base[(size_t)gi * D + gj] + acc[i][j] - coef * mi * mj) * invden;
            }
        }
    }
}

// ---------------- blocked-parallel diag factor + triangular inverse ----------------
// 256 threads. 32-wide panels with deferred scaling, parallel rank-32 trailing
// update, then log-depth inversion: 4x 32-col inverses -> 64 combine -> 128 combine.
__global__ void k_chol_diag(int kb) {
    extern __shared__ float sh[];
    float* A = sh;                    // 128 x 129 (L in progress)
    float* V = sh + 128 * 129;        // 128 x 129 (inverse, init 0)
    float* T = sh + 2 * 128 * 129;    // 64 x 65 temp
    __shared__ float sdiag[128];
    int c = blockIdx.x;
    int tid = threadIdx.x;
    float* Sg = d_sigma + (size_t)c * D * D;
    const size_t gbase = (size_t)(kb * BS) * D + kb * BS;

    for (int idx = tid; idx < BS * BS; idx += 256) {
        int r = idx >> 7, col = idx & 127;
        A[r * 129 + col] = (col <= r) ? Sg[gbase + (size_t)r * D + col] : 0.f;
        V[r * 129 + col] = 0.f;
    }
    __syncthreads();

    for (int p0 = 0; p0 < BS; p0 += 32) {
        // in-panel factorization with deferred scaling (rank-1 via v v^T / d)
        for (int jj = 0; jj < 32; jj++) {
            int j = p0 + jj;
            float dj = A[j * 129 + j];
            if (tid == 0) sdiag[j] = dj;
            float ir = 1.f / dj;
            if (tid < BS && tid > j) {
                int r = tid;
                float lr = A[r * 129 + j] * ir;
                for (int c2 = j + 1; c2 < p0 + 32; c2++)
                    if (r >= c2) A[r * 129 + c2] -= lr * A[c2 * 129 + j];
            }
            __syncthreads();
        }
        // scale panel columns: L[:,j] = v/sqrt(d_j), diag = sqrt(d_j)
        for (int idx = tid; idx < (BS - p0) * 32; idx += 256) {
            int rr = idx >> 5, jj = idx & 31;
            int r = p0 + rr, j = p0 + jj;
            if (r > j) A[r * 129 + j] *= rsqrtf(sdiag[j]);
            else if (r == j) A[j * 129 + j] = sqrtf(sdiag[j]);
        }
        __syncthreads();
        // trailing syrk on rows/cols >= p0+32 (lower only)
        int t0 = p0 + 32;
        if (t0 < BS) {
            int nt = BS - t0;
            for (int idx = tid; idx < nt * nt; idx += 256) {
                int ri = idx / nt, ci = idx % nt;
                int r = t0 + ri, c2 = t0 + ci;
                if (c2 <= r) {
                    float s = 0.f;
#pragma unroll 8
                    for (int q = p0; q < p0 + 32; q++)
                        s = fmaf(A[r * 129 + q], A[c2 * 129 + q], s);
                    A[r * 129 + c2] -= s;
                }
            }
            __syncthreads();
        }
    }
    // store L (lower)
    for (int idx = tid; idx < BS * BS; idx += 256) {
        int r = idx >> 7, col = idx & 127;
        if (col <= r) Sg[gbase + (size_t)r * D + col] = A[r * 129 + col];
    }
    // 4x (32x32) diagonal inverses: one thread per column, columns independent
    if (tid < 128) {
        int b = tid >> 5, tt = tid & 31;
        int base = b * 32;
        int gc = base + tt;
        V[gc * 129 + gc] = 1.f / A[gc * 129 + gc];
        for (int r = tt + 1; r < 32; r++) {
            int gr = base + r;
            float s = 0.f;
            for (int q = tt; q < r; q++)
                s = fmaf(A[gr * 129 + base + q], V[(base + q) * 129 + gc], s);
            V[gr * 129 + gc] = -s / A[gr * 129 + gr];
        }
    }
    __syncthreads();
    // level-1 combines: pairs (1,0) and (3,2) at 32 granularity
    for (int idx = tid; idx < 2 * 32 * 32; idx += 256) {
        int p = idx >> 10, rem = idx & 1023;
        int i = rem >> 5, j2 = rem & 31;
        int rb = (2 * p + 1) * 32, cb = 2 * p * 32;
        float s = 0.f;
        for (int q = j2; q < 32; q++)
            s = fmaf(A[(rb + i) * 129 + cb + q], V[(cb + q) * 129 + cb + j2], s);
        T[p * (32 * 33) + i * 33 + j2] = s;
    }
    __syncthreads();
    for (int idx = tid; idx < 2 * 32 * 32; idx += 256) {
        int p = idx >> 10, rem = idx & 1023;
        int i = rem >> 5, j2 = rem & 31;
        int rb = (2 * p + 1) * 32;
        float s = 0.f;
        for (int q = 0; q <= i; q++)
            s = fmaf(V[(rb + i) * 129 + rb + q], T[p * (32 * 33) + q * 33 + j2], s);
        V[(rb + i) * 129 + 2 * p * 32 + j2] = -s;
    }
    __syncthreads();
    // level-2 combine: V[64:128][0:64] = -V_hi * (A[64:][0:64] * V_lo)
    for (int idx = tid; idx < 64 * 64; idx += 256) {
        int i = idx >> 6, j2 = idx & 63;
        float s = 0.f;
        for (int q = j2; q < 64; q++)
            s = fmaf(A[(64 + i) * 129 + q], V[q * 129 + j2], s);
        T[i * 65 + j2] = s;
    }
    __syncthreads();
    for (int idx = tid; idx < 64 * 64; idx += 256) {
        int i = idx >> 6, j2 = idx & 63;
        float s = 0.f;
        for (int q = 0; q <= i; q++)
            s = fmaf(V[(64 + i) * 129 + 64 + q], T[q * 65 + j2], s);
        V[(64 + i) * 129 + j2] = -s;
    }
    __syncthreads();
    float* iLg = d_invL + (size_t)c * D * D;
    for (int idx = tid; idx < BS * BS; idx += 256) {
        int r = idx >> 7, col = idx & 127;
        iLg[gbase + (size_t)r * D + col] = V[r * 129 + col];
    }
}

// panel: L(bi,kb) = A(bi,kb) * invLkk^T
__global__ void k_panel(int kb) {
    int bi = blockIdx.x, c = blockIdx.y;
    if (bi <= kb) return;
    __shared__ float As[32 * 129], Bs[32 * 129];
    int tid = threadIdx.x, tx = tid & 15, ty = tid >> 4;
    int r0 = ty * 8, c0 = tx * 8;
    float acc[8][8] = {};
    float* Sg = d_sigma + (size_t)c * D * D;
    const float* iL = d_invL + (size_t)c * D * D;
    for (int kc = 0; kc < BS; kc += 32) {
        __syncthreads();
#pragma unroll
        for (int l = 0; l < 16; l++) {
            int idx = tid + 256 * l;
            int r = idx >> 5, kk = idx & 31;
            As[kk * 129 + r] = Sg[(size_t)(bi * BS + r) * D + kb * BS + kc + kk];
            Bs[kk * 129 + r] = iL[(size_t)(kb * BS + r) * D + kb * BS + kc + kk];
        }
        __syncthreads();
        mm32(As, Bs, r0, c0, acc);
    }
    __syncthreads();
#pragma unroll
    for (int i = 0; i < 8; i++)
#pragma unroll
        for (int j = 0; j < 8; j++)
            Sg[(size_t)(bi * BS + r0 + i) * D + kb * BS + c0 + j] = acc[i][j];
}

// trailing update: A(bi,bj) -= P_bi P_bj^T  for kb < bj <= bi
__global__ void k_syrk(int kb) {
    int bi = blockIdx.x, bj = blockIdx.y, c = blockIdx.z;
    if (bj <= kb || bj > bi) return;
    __shared__ float As[32 * 129], Bs[32 * 129];
    int tid = threadIdx.x, tx = tid & 15, ty = tid >> 4;
    int r0 = ty * 8, c0 = tx * 8;
    float acc[8][8] = {};
    float* Sg = d_sigma + (size_t)c * D * D;
    for (int kc = 0; kc < BS; kc += 32) {
        __syncthreads();
#pragma unroll
        for (int l = 0; l < 16; l++) {
            int idx = tid + 256 * l;
            int r = idx >> 5, kk = idx & 31;
            As[kk * 129 + r] = Sg[(size_t)(bi * BS + r) * D + kb * BS + kc + kk];
            Bs[kk * 129 + r] = Sg[(size_t)(bj * BS + r) * D + kb * BS + kc + kk];
        }
        __syncthreads();
        mm32(As, Bs, r0, c0, acc);
    }
    __syncthreads();
#pragma unroll
    for (int i = 0; i < 8; i++) {
        int gi = bi * BS + r0 + i;
#pragma unroll
        for (int j = 0; j < 8; j++) {
            int gj = bj * BS + c0 + j;
            if (bi != bj || gj <= gi)
                Sg[(size_t)gi * D + gj] -= acc[i][j];
        }
    }
}

// ---------------- recursive-doubling trtri (levels h=1,2,4 in 128-blocks) ----------------
// T = B * iA   (B = L[(2p+1)h : +h][2ph : +h],  iA = inv of leading diag block)
__global__ void k_rdT(int h) {
    int ti = blockIdx.x / h, tj = blockIdx.x % h;
    int p = blockIdx.y, c = blockIdx.z;
    __shared__ float As[32 * 129], Bs[32 * 129];
    int tid = threadIdx.x, tx = tid & 15, ty = tid >> 4;
    int r0 = ty * 8, c0 = tx * 8;
    float acc[8][8] = {};
    const float* Sg = d_sigma + (size_t)c * D * D;
    const float* iL = d_invL + (size_t)c * D * D;
    int rowb = ((2 * p + 1) * h + ti) * BS;
    int colb = 2 * p * h * BS;
    for (int kt = tj; kt < h; kt++) {          // iA(kt,tj) nonzero iff kt >= tj
        for (int kc = 0; kc < BS; kc += 32) {
            int k0 = colb + kt * BS + kc;
            __syncthreads();
#pragma unroll
            for (int l = 0; l < 16; l++) {
                int idx = tid + 256 * l;
                { int r = idx >> 5, kk = idx & 31;
                  As[kk * 129 + r] = Sg[(size_t)(rowb + r) * D + k0 + kk]; }
                { int kk = idx >> 7, j = idx & 127;
                  Bs[kk * 129 + j] = iL[(size_t)(k0 + kk) * D + colb + tj * BS + j]; }
            }
            __syncthreads();
            mm32(As, Bs, r0, c0, acc);
        }
    }
    float* Tg = d_T + (size_t)c * 512 * 512 + (size_t)p * (h * BS) * (h * BS);
#pragma unroll
    for (int i = 0; i < 8; i++)
#pragma unroll
        for (int j = 0; j < 8; j++)
            Tg[(size_t)(ti * BS + r0 + i) * (h * BS) + tj * BS + c0 + j] = acc[i][j];
}

// iL[(2p+1)h+ti][2ph+tj] = -iC * T   (iC = trailing diag inverse, lower)
__global__ void k_rdW(int h) {
    int ti = blockIdx.x / h, tj = blockIdx.x % h;
    int p = blockIdx.y, c = blockIdx.z;
    __shared__ float As[32 * 129], Bs[32 * 129];
    int tid = threadIdx.x, tx = tid & 15, ty = tid >> 4;
    int r0 = ty * 8, c0 = tx * 8;
    float acc[8][8] = {};
    float* iL = d_invL + (size_t)c * D * D;
    const float* Tg = d_T + (size_t)c * 512 * 512 + (size_t)p * (h * BS) * (h * BS);
    int rbase = (2 * p + 1) * h * BS;
    int rowb = rbase + ti * BS;
    int colb = 2 * p * h * BS;
    for (int kt = 0; kt <= ti; kt++) {         // iC(ti,kt) nonzero iff kt <= ti
        for (int kc = 0; kc < BS; kc += 32) {
            __syncthreads();
#pragma unroll
            for (int l = 0; l < 16; l++) {
                int idx = tid + 256 * l;
                { int r = idx >> 5, kk = idx & 31;
                  As[kk * 129 + r] = iL[(size_t)(rowb + r) * D + rbase + kt * BS + kc + kk]; }
                { int kk = idx >> 7, j = idx & 127;
                  Bs[kk * 129 + j] = Tg[(size_t)(kt * BS + kc + kk) * (h * BS) + tj * BS + j]; }
            }
            __syncthreads();
            mm32(As, Bs, r0, c0, acc);
        }
    }
    __syncthreads();
#pragma unroll
    for (int i = 0; i < 8; i++)
#pragma unroll
        for (int j = 0; j < 8; j++)
            iL[(size_t)(rowb + r0 + i) * D + colb + tj * BS + c0 + j] = -acc[i][j];
}

// 0.1 * ||xq - mu_c||^2
__global__ void k_nd(const float* __restrict__ Xq) {
    int c = blockIdx.y;
    int warp = threadIdx.x >> 5, lane = threadIdx.x & 31;
    int mr = blockIdx.x * 8 + warp;
    const float* xq = Xq + (size_t)mr * D;
    const float* mu = d_mu + c * D;
    float s = 0.f;
    for (int k = lane; k < D; k += 32) {
        float df = xq[k] - mu[k];
        s = fmaf(df, df, s);
    }
#pragma unroll
    for (int o = 16; o; o >>= 1) s += __shfl_xor_sync(0xffffffffu, s, o);
    if (!lane) d_acc[(size_t)mr * NC + c] = 0.1f * s;
}

// ---------------- TF32 tensor-core predict ----------------
__device__ __forceinline__ unsigned f2tf(float f) {
    unsigned u;
    asm("cvt.rna.tf32.f32 %0, %1;" : "=r"(u) : "f"(f));
    return u;
}

__global__ void __launch_bounds__(256, 2) k_sq(const float* __restrict__ Xq,
                                               float* __restrict__ out) {
    int mb = blockIdx.x, c = blockIdx.y;
    int m0 = mb * BS;
    __shared__ unsigned Ws[128 * 33];
    __shared__ unsigned Ds[128 * 33];
    __shared__ float red[4][128];
    __shared__ float colAcc[128];
    int tid = threadIdx.x, lane = tid & 31, w = tid >> 5;
    int wr = w >> 1, wc = w & 1;
    const float* iL = d_invL + (size_t)c * D * D;
    const float* mu = d_mu + c * D;
    if (tid < 128) colAcc[tid] = 0.f;

    float cf[2][8][4];
    for (int bi = 0; bi < NB; bi++) {
#pragma unroll
        for (int mt = 0; mt < 2; mt++)
#pragma unroll
            for (int nt = 0; nt < 8; nt++)
#pragma unroll
                for (int r = 0; r < 4; r++) cf[mt][nt][r] = 0.f;

        for (int kt = 0; kt <= bi; kt++) {
            for (int kc = 0; kc < BS; kc += 32) {
                int k0 = kt * BS + kc;
                __syncthreads();
#pragma unroll
                for (int l = 0; l < 16; l++) {
                    int idx = tid + 256 * l;
                    int r = idx >> 5, kk = idx & 31;
                    Ws[r * 33 + kk] = f2tf(iL[(size_t)(bi * BS + r) * D + k0 + kk]);
                    Ds[r * 33 + kk] =
                        f2tf(Xq[(size_t)(m0 + r) * D + k0 + kk] - mu[k0 + kk]);
                }
                __syncthreads();
#pragma unroll
                for (int ks = 0; ks < 4; ks++) {
                    int kl = ks * 8;
                    unsigned a[2][4];
#pragma unroll
                    for (int mt = 0; mt < 2; mt++) {
                        int row = wr * 32 + mt * 16 + (lane >> 2);
                        int col = kl + (lane & 3);
                        a[mt][0] = Ws[row * 33 + col];
                        a[mt][1] = Ws[(row + 8) * 33 + col];
                        a[mt][2] = Ws[row * 33 + col + 4];
                        a[mt][3] = Ws[(row + 8) * 33 + col + 4];
                    }
#pragma unroll
                    for (int nt = 0; nt < 8; nt++) {
                        int q = wc * 64 + nt * 8 + (lane >> 2);
                        int kq = kl + (lane & 3);
                        unsigned b0 = Ds[q * 33 + kq];
                        unsigned b1 = Ds[q * 33 + kq + 4];
#pragma unroll
                        for (int mt = 0; mt < 2; mt++) {
                            asm volatile(
                                "mma.sync.aligned.m16n8k8.row.col.f32.tf32.tf32.f32 "
                                "{%0,%1,%2,%3},{%4,%5,%6,%7},{%8,%9},{%0,%1,%2,%3};"
                                : "+f"(cf[mt][nt][0]), "+f"(cf[mt][nt][1]),
                                  "+f"(cf[mt][nt][2]), "+f"(cf[mt][nt][3])
                                : "r"(a[mt][0]), "r"(a[mt][1]), "r"(a[mt][2]),
                                  "r"(a[mt][3]), "r"(b0), "r"(b1));
                        }
                    }
                }
            }
        }
        float qs[8][2];
#pragma unroll
        for (int nt = 0; nt < 8; nt++)
#pragma unroll
            for (int e = 0; e < 2; e++) {
                float s = 0.f;
#pragma unroll
                for (int mt = 0; mt < 2; mt++) {
                    float v0 = cf[mt][nt][e], v2 = cf[mt][nt][2 + e];
                    s = fmaf(v0, v0, s);
                    s = fmaf(v2, v2, s);
                }
                s += __shfl_xor_sync(0xffffffffu, s, 4);
                s += __shfl_xor_sync(0xffffffffu, s, 8);
                s += __shfl_xor_sync(0xffffffffu, s, 16);
                qs[nt][e] = s;
            }
        __syncthreads();
        if ((lane >> 2) == 0) {
#pragma unroll
            for (int nt = 0; nt < 8; nt++)
#pragma unroll
                for (int e = 0; e < 2; e++) {
                    int q = wc * 64 + nt * 8 + (lane & 3) * 2 + e;
                    red[wr][q] = qs[nt][e];
                }
        }
        __syncthreads();
        if (tid < 128)
            colAcc[tid] += red[0][tid] + red[1][tid] + red[2][tid] + red[3][tid];
    }
    __syncthreads();
    if (tid < 128) {
        int mr = m0 + tid;
        out[(size_t)mr * NC + c] = -(0.9f * colAcc[tid] + d_acc[(size_t)mr * NC + c]);
    }
}

// ---------------- launch ----------------
extern "C" void kernel_launch(void* const* d_in, const int* in_sizes, int n_in,
                              void* d_out, int out_size) {
    const float* X    = (const float*)d_in[0];
    const int*   y    = (const int*)  d_in[1];
    const float* Xq   = (const float*)d_in[2];
    const float* m    = (const float*)d_in[3];
    const float* kap  = (const float*)d_in[4];
    const float* nu   = (const float*)d_in[5];
    const float* diag = (const float*)d_in[6];
    const float* TL   = (const float*)d_in[7];
    float* out = (float*)d_out;
    (void)in_sizes; (void)n_in; (void)out_size;

    const int chol_smem = (2 * 128 * 129 + 64 * 65) * 4;
    cudaFuncSetAttribute(k_chol_diag, cudaFuncAttributeMaxDynamicSharedMemorySize,
                         chol_smem);

    k_count<<<1, 1024>>>(y);
    k_rank<<<16, 256>>>(y);
    k_scatter<<<NS, 256>>>(X);
    k_mu<<<dim3(D / 256, NC), 256>>>(m, kap);
    k_base<<<dim3(NB, NB), 256>>>(diag, TL, m, kap);
    k_sigma<<<dim3(NB, NB, NC), 256>>>(kap, nu);
    for (int kb = 0; kb < NB; kb++) {
        k_chol_diag<<<NC, 256, chol_smem>>>(kb);
        if (kb < NB - 1) {
            k_panel<<<dim3(NB, NC), 256>>>(kb);
            k_syrk<<<dim3(NB, NB, NC), 256>>>(kb);
        }
    }
    for (int h = 1; h <= 4; h *= 2) {
        int pairs = NB / (2 * h);
        k_rdT<<<dim3(h * h, pairs, NC), 256>>>(h);
        k_rdW<<<dim3(h * h, pairs, NC), 256>>>(h);
    }
    k_nd<<<dim3(MQ / 8, NC), 256>>>(Xq);
    k_sq<<<dim3(MQ / BS, NC), 256>>>(Xq, out);
}

// round 13
// speedup vs baseline: 2.1467x; 1.1528x over previous
#include <cuda_runtime.h>
#include <math.h>
#include <stdint.h>

#define D  1024
#define NC 16
#define NS 4096
#define MQ 4096
#define BS 128
#define NB 8
#define WSTR 68   // padded row stride (floats) for pair-layout tiles

// ---------------- scratch (device globals: allocation-free contract) ----------------
__device__ float d_Xs[(size_t)NS * D];
__device__ int   d_counts[NC];
__device__ int   d_offsets[NC + 1];
__device__ int   d_dst[NS];
__device__ float d_mu[NC * D];
__device__ float d_base[(size_t)D * D];
__device__ float d_sigma[(size_t)NC * D * D];   // sigma -> cholesky L (lower)
__device__ float d_invL[(size_t)NC * D * D];    // L^-1 (lower, upper zeroed)
__device__ float d_acc[(size_t)MQ * NC];
__device__ float d_T[(size_t)NC * 512 * 512];   // recursive-doubling scratch

// ---------------- small setup kernels ----------------
__global__ void k_count(const int* __restrict__ y) {
    __shared__ int cnt[NC];
    int t = threadIdx.x;
    if (t < NC) cnt[t] = 0;
    __syncthreads();
    for (int n = t; n < NS; n += blockDim.x) atomicAdd(&cnt[y[n]], 1);
    __syncthreads();
    if (t == 0) {
        int off = 0;
        for (int c = 0; c < NC; c++) { d_counts[c] = cnt[c]; d_offsets[c] = off; off += cnt[c]; }
        d_offsets[NC] = off;
    }
}

__global__ void k_rank(const int* __restrict__ y) {
    __shared__ int sy[NS];
    for (int i = threadIdx.x; i < NS; i += blockDim.x) sy[i] = y[i];
    __syncthreads();
    int n = blockIdx.x * blockDim.x + threadIdx.x;
    int c = sy[n];
    int r = 0;
    for (int p = 0; p < n; p++) r += (sy[p] == c);
    d_dst[n] = d_offsets[c] + r;
}

__global__ void k_scatter(const float* __restrict__ X) {
    int n = blockIdx.x;
    int dst = d_dst[n];
    const float* src = X + (size_t)n * D;
    float* dp = d_Xs + (size_t)dst * D;
    for (int j = threadIdx.x; j < D; j += blockDim.x) dp[j] = src[j];
}

__global__ void k_mu(const float* __restrict__ m, const float* __restrict__ kappa) {
    int c = blockIdx.y;
    int j = blockIdx.x * blockDim.x + threadIdx.x;
    int ks = d_offsets[c], ke = d_offsets[c + 1];
    float s = 0.f;
    for (int r = ks; r < ke; r++) s += d_Xs[(size_t)r * D + j];
    float kap = fabsf(*kappa) + 1e-6f;
    float Nj = (float)(ke - ks);
    d_mu[c * D + j] = (kap * m[j] + s) / (kap + Nj);
}

// ---------------- shared GEMM micro-kernel ----------------
__device__ __forceinline__ void mm32(const float* As, const float* Bs, int r0, int c0,
                                     float acc[8][8]) {
#pragma unroll 4
    for (int kk = 0; kk < 32; kk++) {
        float a[8], b[8];
#pragma unroll
        for (int u = 0; u < 8; u++) a[u] = As[kk * 129 + r0 + u];
#pragma unroll
        for (int u = 0; u < 8; u++) b[u] = Bs[kk * 129 + c0 + u];
#pragma unroll
        for (int i = 0; i < 8; i++)
#pragma unroll
            for (int j = 0; j < 8; j++) acc[i][j] = fmaf(a[i], b[j], acc[i][j]);
    }
}

__device__ __forceinline__ float Lval(const float* diag, const float* TL, int i, int k) {
    if (k < i) return TL[(size_t)i * D + k];
    if (k == i) return fabsf(diag[i]);
    return 0.f;
}

// base = L L^T + kap * m m^T  (lower tiles only)
__global__ void k_base(const float* __restrict__ diag, const float* __restrict__ TL,
                       const float* __restrict__ m, const float* __restrict__ kappa) {
    int bi = blockIdx.x, bj = blockIdx.y;
    if (bj > bi) return;
    __shared__ float As[32 * 129], Bs[32 * 129];
    int tid = threadIdx.x, tx = tid & 15, ty = tid >> 4;
    int r0 = ty * 8, c0 = tx * 8;
    float acc[8][8] = {};
    int kmax = (bj + 1) * BS;
    for (int kc = 0; kc < kmax; kc += 32) {
        __syncthreads();
#pragma unroll
        for (int l = 0; l < 16; l++) {
            int idx = tid + 256 * l;
            int i = idx >> 5, kk = idx & 31;
            As[kk * 129 + i] = Lval(diag, TL, bi * BS + i, kc + kk);
            Bs[kk * 129 + i] = Lval(diag, TL, bj * BS + i, kc + kk);
        }
        __syncthreads();
        mm32(As, Bs, r0, c0, acc);
    }
    float kap = fabsf(*kappa) + 1e-6f;
#pragma unroll
    for (int i = 0; i < 8; i++) {
        int gi = bi * BS + r0 + i;
#pragma unroll
        for (int j = 0; j < 8; j++) {
            int gj = bj * BS + c0 + j;
            if (gj <= gi)
                d_base[(size_t)gi * D + gj] = acc[i][j] + kap * m[gi] * m[gj];
        }
    }
}

// sigma[c] lower = (base + S_c - (kap+Nj) mu mu^T) / (nu_ + Nj + d + 2)
__global__ void k_sigma(const float* __restrict__ kappa, const float* __restrict__ nu) {
    int bi = blockIdx.x, bj = blockIdx.y, c = blockIdx.z;
    if (bj > bi) return;
    __shared__ float As[32 * 129], Bs[32 * 129];
    int tid = threadIdx.x, tx = tid & 15, ty = tid >> 4;
    int r0 = ty * 8, c0 = tx * 8;
    float acc[8][8] = {};
    int ks = d_offsets[c], ke = d_offsets[c + 1];
    for (int k0 = ks; k0 < ke; k0 += 32) {
        __syncthreads();
#pragma unroll
        for (int l = 0; l < 16; l++) {
            int idx = tid + 256 * l;
            int kk = idx >> 7, i = idx & 127;
            int krow = k0 + kk;
            float av = 0.f, bv = 0.f;
            if (krow < ke) {
                av = d_Xs[(size_t)krow * D + bi * BS + i];
                bv = d_Xs[(size_t)krow * D + bj * BS + i];
            }
            As[kk * 129 + i] = av;
            Bs[kk * 129 + i] = bv;
        }
        __syncthreads();
        mm32(As, Bs, r0, c0, acc);
    }
    float kap = fabsf(*kappa) + 1e-6f;
    float Nj = (float)(ke - ks);
    float nuv = fmaxf(*nu, (float)(D - 1) + 1e-6f);
    float invden = 1.f / (nuv + Nj + (float)D + 2.f);
    float coef = kap + Nj;
    float* Sg = d_sigma + (size_t)c * D * D;
#pragma unroll
    for (int i = 0; i < 8; i++) {
        int gi = bi * BS + r0 + i;
        float mi = d_mu[c * D + gi];
#pragma unroll
        for (int j = 0; j < 8; j++) {
            int gj = bj * BS + c0 + j;
            if (gj <= gi) {
                float mj = d_mu[c * D + gj];
                Sg[(size_t)gi * D + gj] =
                    (d_base[(size_t)gi * D + gj] + acc[i][j] - coef * mi * mj) * invden;
            }
        }
    }
}

// ---------------- blocked-parallel diag factor + triangular inverse ----------------
__global__ void k_chol_diag(int kb) {
    extern __shared__ float sh[];
    float* A = sh;
    float* V = sh + 128 * 129;
    float* T = sh + 2 * 128 * 129;
    __shared__ float sdiag[128];
    int c = blockIdx.x;
    int tid = threadIdx.x;
    float* Sg = d_sigma + (size_t)c * D * D;
    const size_t gbase = (size_t)(kb * BS) * D + kb * BS;

    for (int idx = tid; idx < BS * BS; idx += 256) {
        int r = idx >> 7, col = idx & 127;
        A[r * 129 + col] = (col <= r) ? Sg[gbase + (size_t)r * D + col] : 0.f;
        V[r * 129 + col] = 0.f;
    }
    __syncthreads();

    for (int p0 = 0; p0 < BS; p0 += 32) {
        for (int jj = 0; jj < 32; jj++) {
            int j = p0 + jj;
            float dj = A[j * 129 + j];
            if (tid == 0) sdiag[j] = dj;
            float ir = 1.f / dj;
            if (tid < BS && tid > j) {
                int r = tid;
                float lr = A[r * 129 + j] * ir;
                for (int c2 = j + 1; c2 < p0 + 32; c2++)
                    if (r >= c2) A[r * 129 + c2] -= lr * A[c2 * 129 + j];
            }
            __syncthreads();
        }
        for (int idx = tid; idx < (BS - p0) * 32; idx += 256) {
            int rr = idx >> 5, jj = idx & 31;
            int r = p0 + rr, j = p0 + jj;
            if (r > j) A[r * 129 + j] *= rsqrtf(sdiag[j]);
            else if (r == j) A[j * 129 + j] = sqrtf(sdiag[j]);
        }
        __syncthreads();
        int t0 = p0 + 32;
        if (t0 < BS) {
            int nt = BS - t0;
            for (int idx = tid; idx < nt * nt; idx += 256) {
                int ri = idx / nt, ci = idx % nt;
                int r = t0 + ri, c2 = t0 + ci;
                if (c2 <= r) {
                    float s = 0.f;
#pragma unroll 8
                    for (int q = p0; q < p0 + 32; q++)
                        s = fmaf(A[r * 129 + q], A[c2 * 129 + q], s);
                    A[r * 129 + c2] -= s;
                }
            }
            __syncthreads();
        }
    }
    for (int idx = tid; idx < BS * BS; idx += 256) {
        int r = idx >> 7, col = idx & 127;
        if (col <= r) Sg[gbase + (size_t)r * D + col] = A[r * 129 + col];
    }
    if (tid < 128) {
        int b = tid >> 5, tt = tid & 31;
        int base = b * 32;
        int gc = base + tt;
        V[gc * 129 + gc] = 1.f / A[gc * 129 + gc];
        for (int r = tt + 1; r < 32; r++) {
            int gr = base + r;
            float s = 0.f;
            for (int q = tt; q < r; q++)
                s = fmaf(A[gr * 129 + base + q], V[(base + q) * 129 + gc], s);
            V[gr * 129 + gc] = -s / A[gr * 129 + gr];
        }
    }
    __syncthreads();
    for (int idx = tid; idx < 2 * 32 * 32; idx += 256) {
        int p = idx >> 10, rem = idx & 1023;
        int i = rem >> 5, j2 = rem & 31;
        int rb = (2 * p + 1) * 32, cb = 2 * p * 32;
        float s = 0.f;
        for (int q = j2; q < 32; q++)
            s = fmaf(A[(rb + i) * 129 + cb + q], V[(cb + q) * 129 + cb + j2], s);
        T[p * (32 * 33) + i * 33 + j2] = s;
    }
    __syncthreads();
    for (int idx = tid; idx < 2 * 32 * 32; idx += 256) {
        int p = idx >> 10, rem = idx & 1023;
        int i = rem >> 5, j2 = rem & 31;
        int rb = (2 * p + 1) * 32;
        float s = 0.f;
        for (int q = 0; q <= i; q++)
            s = fmaf(V[(rb + i) * 129 + rb + q], T[p * (32 * 33) + q * 33 + j2], s);
        V[(rb + i) * 129 + 2 * p * 32 + j2] = -s;
    }
    __syncthreads();
    for (int idx = tid; idx < 64 * 64; idx += 256) {
        int i = idx >> 6, j2 = idx & 63;
        float s = 0.f;
        for (int q = j2; q < 64; q++)
            s = fmaf(A[(64 + i) * 129 + q], V[q * 129 + j2], s);
        T[i * 65 + j2] = s;
    }
    __syncthreads();
    for (int idx = tid; idx < 64 * 64; idx += 256) {
        int i = idx >> 6, j2 = idx & 63;
        float s = 0.f;
        for (int q = 0; q <= i; q++)
            s = fmaf(V[(64 + i) * 129 + 64 + q], T[q * 65 + j2], s);
        V[(64 + i) * 129 + j2] = -s;
    }
    __syncthreads();
    float* iLg = d_invL + (size_t)c * D * D;
    for (int idx = tid; idx < BS * BS; idx += 256) {
        int r = idx >> 7, col = idx & 127;
        iLg[gbase + (size_t)r * D + col] = V[r * 129 + col];
    }
}

// panel: L(bi,kb) = A(bi,kb) * invLkk^T
__global__ void k_panel(int kb) {
    int bi = blockIdx.x, c = blockIdx.y;
    if (bi <= kb) return;
    __shared__ float As[32 * 129], Bs[32 * 129];
    int tid = threadIdx.x, tx = tid & 15, ty = tid >> 4;
    int r0 = ty * 8, c0 = tx * 8;
    float acc[8][8] = {};
    float* Sg = d_sigma + (size_t)c * D * D;
    const float* iL = d_invL + (size_t)c * D * D;
    for (int kc = 0; kc < BS; kc += 32) {
        __syncthreads();
#pragma unroll
        for (int l = 0; l < 16; l++) {
            int idx = tid + 256 * l;
            int r = idx >> 5, kk = idx & 31;
            As[kk * 129 + r] = Sg[(size_t)(bi * BS + r) * D + kb * BS + kc + kk];
            Bs[kk * 129 + r] = iL[(size_t)(kb * BS + r) * D + kb * BS + kc + kk];
        }
        __syncthreads();
        mm32(As, Bs, r0, c0, acc);
    }
    __syncthreads();
#pragma unroll
    for (int i = 0; i < 8; i++)
#pragma unroll
        for (int j = 0; j < 8; j++)
            Sg[(size_t)(bi * BS + r0 + i) * D + kb * BS + c0 + j] = acc[i][j];
}

// trailing update: A(bi,bj) -= P_bi P_bj^T
__global__ void k_syrk(int kb) {
    int bi = blockIdx.x, bj = blockIdx.y, c = blockIdx.z;
    if (bj <= kb || bj > bi) return;
    __shared__ float As[32 * 129], Bs[32 * 129];
    int tid = threadIdx.x, tx = tid & 15, ty = tid >> 4;
    int r0 = ty * 8, c0 = tx * 8;
    float acc[8][8] = {};
    float* Sg = d_sigma + (size_t)c * D * D;
    for (int kc = 0; kc < BS; kc += 32) {
        __syncthreads();
#pragma unroll
        for (int l = 0; l < 16; l++) {
            int idx = tid + 256 * l;
            int r = idx >> 5, kk = idx & 31;
            As[kk * 129 + r] = Sg[(size_t)(bi * BS + r) * D + kb * BS + kc + kk];
            Bs[kk * 129 + r] = Sg[(size_t)(bj * BS + r) * D + kb * BS + kc + kk];
        }
        __syncthreads();
        mm32(As, Bs, r0, c0, acc);
    }
    __syncthreads();
#pragma unroll
    for (int i = 0; i < 8; i++) {
        int gi = bi * BS + r0 + i;
#pragma unroll
        for (int j = 0; j < 8; j++) {
            int gj = bj * BS + c0 + j;
            if (bi != bj || gj <= gi)
                Sg[(size_t)gi * D + gj] -= acc[i][j];
        }
    }
}

// ---------------- recursive-doubling trtri ----------------
__global__ void k_rdT(int h) {
    int ti = blockIdx.x / h, tj = blockIdx.x % h;
    int p = blockIdx.y, c = blockIdx.z;
    __shared__ float As[32 * 129], Bs[32 * 129];
    int tid = threadIdx.x, tx = tid & 15, ty = tid >> 4;
    int r0 = ty * 8, c0 = tx * 8;
    float acc[8][8] = {};
    const float* Sg = d_sigma + (size_t)c * D * D;
    const float* iL = d_invL + (size_t)c * D * D;
    int rowb = ((2 * p + 1) * h + ti) * BS;
    int colb = 2 * p * h * BS;
    for (int kt = tj; kt < h; kt++) {
        for (int kc = 0; kc < BS; kc += 32) {
            int k0 = colb + kt * BS + kc;
            __syncthreads();
#pragma unroll
            for (int l = 0; l < 16; l++) {
                int idx = tid + 256 * l;
                { int r = idx >> 5, kk = idx & 31;
                  As[kk * 129 + r] = Sg[(size_t)(rowb + r) * D + k0 + kk]; }
                { int kk = idx >> 7, j = idx & 127;
                  Bs[kk * 129 + j] = iL[(size_t)(k0 + kk) * D + colb + tj * BS + j]; }
            }
            __syncthreads();
            mm32(As, Bs, r0, c0, acc);
        }
    }
    float* Tg = d_T + (size_t)c * 512 * 512 + (size_t)p * (h * BS) * (h * BS);
#pragma unroll
    for (int i = 0; i < 8; i++)
#pragma unroll
        for (int j = 0; j < 8; j++)
            Tg[(size_t)(ti * BS + r0 + i) * (h * BS) + tj * BS + c0 + j] = acc[i][j];
}

__global__ void k_rdW(int h) {
    int ti = blockIdx.x / h, tj = blockIdx.x % h;
    int p = blockIdx.y, c = blockIdx.z;
    __shared__ float As[32 * 129], Bs[32 * 129];
    int tid = threadIdx.x, tx = tid & 15, ty = tid >> 4;
    int r0 = ty * 8, c0 = tx * 8;
    float acc[8][8] = {};
    float* iL = d_invL + (size_t)c * D * D;
    const float* Tg = d_T + (size_t)c * 512 * 512 + (size_t)p * (h * BS) * (h * BS);
    int rbase = (2 * p + 1) * h * BS;
    int rowb = rbase + ti * BS;
    int colb = 2 * p * h * BS;
    for (int kt = 0; kt <= ti; kt++) {
        for (int kc = 0; kc < BS; kc += 32) {
            __syncthreads();
#pragma unroll
            for (int l = 0; l < 16; l++) {
                int idx = tid + 256 * l;
                { int r = idx >> 5, kk = idx & 31;
                  As[kk * 129 + r] = iL[(size_t)(rowb + r) * D + rbase + kt * BS + kc + kk]; }
                { int kk = idx >> 7, j = idx & 127;
                  Bs[kk * 129 + j] = Tg[(size_t)(kt * BS + kc + kk) * (h * BS) + tj * BS + j]; }
            }
            __syncthreads();
            mm32(As, Bs, r0, c0, acc);
        }
    }
    __syncthreads();
#pragma unroll
    for (int i = 0; i < 8; i++)
#pragma unroll
        for (int j = 0; j < 8; j++)
            iL[(size_t)(rowb + r0 + i) * D + colb + tj * BS + c0 + j] = -acc[i][j];
}

// 0.1 * ||xq - mu_c||^2
__global__ void k_nd(const float* __restrict__ Xq) {
    int c = blockIdx.y;
    int warp = threadIdx.x >> 5, lane = threadIdx.x & 31;
    int mr = blockIdx.x * 8 + warp;
    const float* xq = Xq + (size_t)mr * D;
    const float* mu = d_mu + c * D;
    float s = 0.f;
    for (int k = lane; k < D; k += 32) {
        float df = xq[k] - mu[k];
        s = fmaf(df, df, s);
    }
#pragma unroll
    for (int o = 16; o; o >>= 1) s += __shfl_xor_sync(0xffffffffu, s, o);
    if (!lane) d_acc[(size_t)mr * NC + c] = 0.1f * s;
}

// ---------------- TF32 mma.sync predict ----------------
__device__ __forceinline__ float f2tf_f(float f) {
    uint32_t u;
    asm("cvt.rna.tf32.f32 %0, %1;" : "=r"(u) : "f"(f));
    return __uint_as_float(u);
}

// Block = 128 queries x 1 class; 8 warps (4 row-groups x 2 query-halves).
// K-chunk 64, pair layout: word (row,k) at row*WSTR + (k&7 pairs with k+... )
// stored as float2 {v[k], v[k+4]} at row*WSTR + ks8 + 2*(k&3) so fragment
// halves (k, k+4) are a single LDS.64. cvt.rna.tf32 applied in fill phase.
__global__ void __launch_bounds__(256, 2) k_sq(const float* __restrict__ Xq,
                                               float* __restrict__ out) {
    extern __shared__ float sh[];
    float* Wp = sh;                       // 128 x WSTR
    float* Dp = sh + 128 * WSTR;          // 128 x WSTR
    float* red = sh + 2 * 128 * WSTR;     // 4 x 128
    float* colAcc = red + 4 * 128;        // 128
    int mb = blockIdx.x, c = blockIdx.y;
    int m0 = mb * BS;
    int tid = threadIdx.x, lane = tid & 31, w = tid >> 5;
    int wr = w >> 1, wc = w & 1;
    const float* iL = d_invL + (size_t)c * D * D;
    const float* mu = d_mu + c * D;
    if (tid < 128) colAcc[tid] = 0.f;

    const int t4 = lane & 3;              // fragment k-lane
    const int r4 = lane >> 2;             // fragment row-lane

    float cf[2][8][4];
    for (int bi = 0; bi < NB; bi++) {
#pragma unroll
        for (int mt = 0; mt < 2; mt++)
#pragma unroll
            for (int nt = 0; nt < 8; nt++)
#pragma unroll
                for (int r = 0; r < 4; r++) cf[mt][nt][r] = 0.f;

        for (int kt = 0; kt <= bi; kt++) {
#pragma unroll 1
            for (int kc2 = 0; kc2 < 2; kc2++) {
                const int k0 = kt * 128 + kc2 * 64;
                __syncthreads();
                // ---- fill W and D tiles: 128 rows x 64 k each, pair layout,
                //      round-to-nearest tf32 applied here (off mainloop) ----
#pragma unroll
                for (int l = 0; l < 4; l++) {
                    int seg = tid + 256 * l;          // 1024 segs of 8 k
                    int row = seg >> 3, ks8 = (seg & 7) * 8;
                    const float* gp = iL + (size_t)(bi * BS + row) * D + k0 + ks8;
                    float4 va = *(const float4*)gp;
                    float4 vb = *(const float4*)(gp + 4);
                    float2* dst = (float2*)(Wp + row * WSTR + ks8);
                    dst[0] = make_float2(f2tf_f(va.x), f2tf_f(vb.x));
                    dst[1] = make_float2(f2tf_f(va.y), f2tf_f(vb.y));
                    dst[2] = make_float2(f2tf_f(va.z), f2tf_f(vb.z));
                    dst[3] = make_float2(f2tf_f(va.w), f2tf_f(vb.w));
                }
#pragma unroll
                for (int l = 0; l < 4; l++) {
                    int seg = tid + 256 * l;
                    int row = seg >> 3, ks8 = (seg & 7) * 8;
                    const float* gp = Xq + (size_t)(m0 + row) * D + k0 + ks8;
                    float4 va = *(const float4*)gp;
                    float4 vb = *(const float4*)(gp + 4);
                    float4 ma = *(const float4*)(mu + k0 + ks8);
                    float4 mb4 = *(const float4*)(mu + k0 + ks8 + 4);
                    va.x -= ma.x; va.y -= ma.y; va.z -= ma.z; va.w -= ma.w;
                    vb.x -= mb4.x; vb.y -= mb4.y; vb.z -= mb4.z; vb.w -= mb4.w;
                    float2* dst = (float2*)(Dp + row * WSTR + ks8);
                    dst[0] = make_float2(f2tf_f(va.x), f2tf_f(vb.x));
                    dst[1] = make_float2(f2tf_f(va.y), f2tf_f(vb.y));
                    dst[2] = make_float2(f2tf_f(va.z), f2tf_f(vb.z));
                    dst[3] = make_float2(f2tf_f(va.w), f2tf_f(vb.w));
                }
                __syncthreads();
                // ---- mainloop: 8 k-steps of m16n8k8, LDS.64 fragments ----
#pragma unroll
                for (int ks = 0; ks < 8; ks++) {
                    float2 aP[2], aQ[2];
#pragma unroll
                    for (int mt = 0; mt < 2; mt++) {
                        int row = wr * 32 + mt * 16 + r4;
                        aP[mt] = *(const float2*)(Wp + row * WSTR + ks * 8 + 2 * t4);
                        aQ[mt] = *(const float2*)(Wp + (row + 8) * WSTR + ks * 8 + 2 * t4);
                    }
#pragma unroll
                    for (int nt = 0; nt < 8; nt++) {
                        int q = wc * 64 + nt * 8 + r4;
                        float2 b = *(const float2*)(Dp + q * WSTR + ks * 8 + 2 * t4);
                        uint32_t b0 = __float_as_uint(b.x), b1 = __float_as_uint(b.y);
#pragma unroll
                        for (int mt = 0; mt < 2; mt++) {
                            asm volatile(
                                "mma.sync.aligned.m16n8k8.row.col.f32.tf32.tf32.f32 "
                                "{%0,%1,%2,%3},{%4,%5,%6,%7},{%8,%9},{%0,%1,%2,%3};"
                                : "+f"(cf[mt][nt][0]), "+f"(cf[mt][nt][1]),
                                  "+f"(cf[mt][nt][2]), "+f"(cf[mt][nt][3])
                                : "r"(__float_as_uint(aP[mt].x)),
                                  "r"(__float_as_uint(aQ[mt].x)),
                                  "r"(__float_as_uint(aP[mt].y)),
                                  "r"(__float_as_uint(aQ[mt].y)),
                                  "r"(b0), "r"(b1));
                        }
                    }
                }
            }
        }
        // square-accumulate Z tile into per-query sums
        float qs[8][2];
#pragma unroll
        for (int nt = 0; nt < 8; nt++)
#pragma unroll
            for (int e = 0; e < 2; e++) {
                float s = 0.f;
#pragma unroll
                for (int mt = 0; mt < 2; mt++) {
                    float v0 = cf[mt][nt][e], v2 = cf[mt][nt][2 + e];
                    s = fmaf(v0, v0, s);
                    s = fmaf(v2, v2, s);
                }
                s += __shfl_xor_sync(0xffffffffu, s, 4);
                s += __shfl_xor_sync(0xffffffffu, s, 8);
                s += __shfl_xor_sync(0xffffffffu, s, 16);
                qs[nt][e] = s;
            }
        __syncthreads();
        if (r4 == 0) {
#pragma unroll
            for (int nt = 0; nt < 8; nt++)
#pragma unroll
                for (int e = 0; e < 2; e++) {
                    int q = wc * 64 + nt * 8 + t4 * 2 + e;
                    red[wr * 128 + q] = qs[nt][e];
                }
        }
        __syncthreads();
        if (tid < 128)
            colAcc[tid] += red[0 * 128 + tid] + red[1 * 128 + tid] +
                           red[2 * 128 + tid] + red[3 * 128 + tid];
    }
    __syncthreads();
    if (tid < 128) {
        int mr = m0 + tid;
        out[(size_t)mr * NC + c] = -(0.9f * colAcc[tid] + d_acc[(size_t)mr * NC + c]);
    }
}

#define SQ_SMEM ((2 * 128 * WSTR + 4 * 128 + 128) * 4)

// ---------------- launch ----------------
extern "C" void kernel_launch(void* const* d_in, const int* in_sizes, int n_in,
                              void* d_out, int out_size) {
    const float* X    = (const float*)d_in[0];
    const int*   y    = (const int*)  d_in[1];
    const float* Xq   = (const float*)d_in[2];
    const float* m    = (const float*)d_in[3];
    const float* kap  = (const float*)d_in[4];
    const float* nu   = (const float*)d_in[5];
    const float* diag = (const float*)d_in[6];
    const float* TL   = (const float*)d_in[7];
    float* out = (float*)d_out;
    (void)in_sizes; (void)n_in; (void)out_size;

    const int chol_smem = (2 * 128 * 129 + 64 * 65) * 4;
    cudaFuncSetAttribute(k_chol_diag, cudaFuncAttributeMaxDynamicSharedMemorySize,
                         chol_smem);
    cudaFuncSetAttribute(k_sq, cudaFuncAttributeMaxDynamicSharedMemorySize, SQ_SMEM);

    k_count<<<1, 1024>>>(y);
    k_rank<<<16, 256>>>(y);
    k_scatter<<<NS, 256>>>(X);
    k_mu<<<dim3(D / 256, NC), 256>>>(m, kap);
    k_base<<<dim3(NB, NB), 256>>>(diag, TL, m, kap);
    k_sigma<<<dim3(NB, NB, NC), 256>>>(kap, nu);
    for (int kb = 0; kb < NB; kb++) {
        k_chol_diag<<<NC, 256, chol_smem>>>(kb);
        if (kb < NB - 1) {
            k_panel<<<dim3(NB, NC), 256>>>(kb);
            k_syrk<<<dim3(NB, NB, NC), 256>>>(kb);
        }
    }
    for (int h = 1; h <= 4; h *= 2) {
        int pairs = NB / (2 * h);
        k_rdT<<<dim3(h * h, pairs, NC), 256>>>(h);
        k_rdW<<<dim3(h * h, pairs, NC), 256>>>(h);
    }
    k_nd<<<dim3(MQ / 8, NC), 256>>>(Xq);
    k_sq<<<dim3(MQ / BS, NC), 256, SQ_SMEM>>>(Xq, out);
}